// round 7
// baseline (speedup 1.0000x reference)
#include <cuda_runtime.h>
#include <cuda_bf16.h>
#include <math.h>
#include <stdint.h>

// Problem constants
#define N1 8
#define N2 8
#define P  1024
#define D  768
#define PH 32
#define PW 32
#define OH 512
#define OW 512

// GEMM tiling (mma.sync path; tcgen05 is unavailable: harness targets sm_100 base)
#define BM 128
#define BN 128
#define BK 64
#define STAGES 3
#define KSTEPS (D / BK)           // 12
#define QSTEPS (P / BN)           // 8
#define NSTEP  (KSTEPS * QSTEPS)  // 96
#define TILE_BYTES  (128 * BK * 2)       // 16384 (128 rows x 128B)
#define STAGE_BYTES (2 * TILE_BYTES)     // 32768
#define SMEM_DYN    (STAGES * STAGE_BYTES)  // 98304

// Scratch (no cudaMalloc allowed)
__device__ __nv_bfloat16 g_Fh[N1 * P * D];  // normalized feats, bf16
__device__ __nv_bfloat16 g_Gh[N2 * P * D];  // normalized nfeats, bf16
__device__ float g_spatch[N1 * N2 * P];     // scores_patch[n][m][p]
__device__ float g_sp[N1 * P];              // mean over m

// ---------------------------------------------------------------------------
// Helpers
// ---------------------------------------------------------------------------
__device__ __forceinline__ uint32_t cvta_s(const void* p) {
    return (uint32_t)__cvta_generic_to_shared(p);
}

#define CPA16(dst, src) \
    asm volatile("cp.async.cg.shared.global [%0], [%1], 16;\n" :: "r"(dst), "l"(src))
#define CPA_COMMIT() asm volatile("cp.async.commit_group;\n" ::: "memory")
#define CPA_WAIT1()  asm volatile("cp.async.wait_group 1;\n" ::: "memory")

__device__ __forceinline__ void ldsm4(uint32_t& r0, uint32_t& r1, uint32_t& r2,
                                      uint32_t& r3, uint32_t a) {
    asm volatile("ldmatrix.sync.aligned.m8n8.x4.shared.b16 {%0,%1,%2,%3}, [%4];\n"
                 : "=r"(r0), "=r"(r1), "=r"(r2), "=r"(r3) : "r"(a));
}

__device__ __forceinline__ void mma16816(float* c, const uint32_t* a, const uint32_t* b) {
    asm volatile(
        "mma.sync.aligned.m16n8k16.row.col.f32.bf16.bf16.f32 "
        "{%0,%1,%2,%3}, {%4,%5,%6,%7}, {%8,%9}, {%0,%1,%2,%3};\n"
        : "+f"(c[0]), "+f"(c[1]), "+f"(c[2]), "+f"(c[3])
        : "r"(a[0]), "r"(a[1]), "r"(a[2]), "r"(a[3]), "r"(b[0]), "r"(b[1]));
}

// Tile row = 64 bf16 = 128B = 8 chunks of 16B. Canonical SW128 swizzle:
// chunk ^= (row & 7). 8 consecutive rows at fixed logical chunk -> 8 distinct
// 16B slots; conflict-free for both cp.async writes and ldmatrix reads.
__device__ __forceinline__ uint32_t swaddr(int row, int ch) {
    return (uint32_t)((row << 7) | (((ch ^ (row & 7)) & 7) << 4));
}

// ---------------------------------------------------------------------------
// Kernel 1: row-normalize -> bf16. grid = 16384 rows, block = 192
// ---------------------------------------------------------------------------
__global__ void norm_k(const float* __restrict__ feats,
                       const float* __restrict__ nfeats) {
    int row = blockIdx.x;
    const float* src;
    __nv_bfloat16* dst;
    if (row < N1 * P) {
        src = feats + (size_t)row * D;
        dst = g_Fh + (size_t)row * D;
    } else {
        int r = row - N1 * P;
        src = nfeats + (size_t)r * D;
        dst = g_Gh + (size_t)r * D;
    }
    int t = threadIdx.x;  // 0..191
    float4 x = *(const float4*)(src + t * 4);
    float s = x.x * x.x + x.y * x.y + x.z * x.z + x.w * x.w;
    #pragma unroll
    for (int off = 16; off; off >>= 1)
        s += __shfl_xor_sync(0xffffffffu, s, off);
    __shared__ float ws[6];
    __shared__ float rnorm_s;
    if ((t & 31) == 0) ws[t >> 5] = s;
    __syncthreads();
    if (t == 0) {
        float tot = 0.f;
        #pragma unroll
        for (int i = 0; i < 6; i++) tot += ws[i];
        rnorm_s = 1.0f / sqrtf(tot);
    }
    __syncthreads();
    float r = rnorm_s;
    __nv_bfloat162 h0 = __floats2bfloat162_rn(x.x * r, x.y * r);
    __nv_bfloat162 h1 = __floats2bfloat162_rn(x.z * r, x.w * r);
    uint2 pk;
    pk.x = *(uint32_t*)&h0;
    pk.y = *(uint32_t*)&h1;
    *(uint2*)(dst + t * 4) = pk;
}

// ---------------------------------------------------------------------------
// Kernel 2: bf16 tensor-core batched GEMM + running max over q.
// grid = (P/BM = 8, 64 pairs), 256 threads = 8 warps (2 m-rows x 4 n-cols),
// warp tile 64m x 32n, mma.m16n8k16, BK=64, 3-stage cp.async pipeline.
// ---------------------------------------------------------------------------
__global__ __launch_bounds__(256, 2)
void gemm_max_k() {
    extern __shared__ __align__(1024) unsigned char smem[];
    const uint32_t sbase = cvta_s(smem);

    const int pair = blockIdx.y;
    const __nv_bfloat16* __restrict__ Fb = g_Fh + (size_t)(pair >> 3) * P * D;
    const __nv_bfloat16* __restrict__ Gb = g_Gh + (size_t)(pair & 7) * P * D;
    const int p0 = blockIdx.x * BM;

    const int tid  = threadIdx.x;
    const int lane = tid & 31;
    const int wid  = tid >> 5;
    const int wrow = (wid >> 2) * 64;  // warp m offset (0 / 64)
    const int wcol = (wid & 3) * 32;   // warp n offset (0..96)

    // loader mapping: thread -> (row = tid>>1, chunk quad = (tid&1)*4)
    const int lrow = tid >> 1;        // 0..127
    const int lq   = (tid & 1) * 4;   // 0 or 4 (four 16B chunks each)

    float acc[4][4][4];
    float cmax[4][2];
    #pragma unroll
    for (int i = 0; i < 4; i++) { cmax[i][0] = -1e30f; cmax[i][1] = -1e30f; }
    #pragma unroll
    for (int i = 0; i < 4; i++)
        #pragma unroll
        for (int j = 0; j < 4; j++)
            #pragma unroll
            for (int e = 0; e < 4; e++) acc[i][j][e] = 0.f;

    // -------- cp.async tile loader for flattened step s --------
    auto load_step = [&](int s) {
        int q0 = (s / KSTEPS) * BN;
        int k0 = (s % KSTEPS) * BK;
        uint32_t Ab = sbase + (s % STAGES) * STAGE_BYTES;
        uint32_t Bb = Ab + TILE_BYTES;
        const __nv_bfloat16* arow = Fb + (size_t)(p0 + lrow) * D + k0;
        const __nv_bfloat16* brow = Gb + (size_t)(q0 + lrow) * D + k0;
        #pragma unroll
        for (int c = 0; c < 4; c++) {
            int ch = lq + c;
            CPA16(Ab + swaddr(lrow, ch), arow + ch * 8);
            CPA16(Bb + swaddr(lrow, ch), brow + ch * 8);
        }
    };

    // prologue
    #pragma unroll
    for (int s = 0; s < STAGES - 1; s++) {
        load_step(s);
        CPA_COMMIT();
    }

    // per-warp ldmatrix lane offsets
    const int mr = lane & 15;        // row-within-16 for ldsm
    const int cl = lane >> 4;        // 16B chunk select (0/1)

    int kc = 0;  // position within current q-pass
    for (int s = 0; s < NSTEP; s++) {
        CPA_WAIT1();
        __syncthreads();
        uint32_t Ab = sbase + (s % STAGES) * STAGE_BYTES;
        uint32_t Bb = Ab + TILE_BYTES;

        #pragma unroll
        for (int hk = 0; hk < 4; hk++) {  // four k16 groups in BK=64
            uint32_t a[4][4], b[4][2];
            #pragma unroll
            for (int i = 0; i < 4; i++)
                ldsm4(a[i][0], a[i][1], a[i][2], a[i][3],
                      Ab + swaddr(wrow + i * 16 + mr, hk * 2 + cl));
            #pragma unroll
            for (int j = 0; j < 2; j++) {
                uint32_t r0, r1, r2, r3;
                ldsm4(r0, r1, r2, r3,
                      Bb + swaddr(wcol + j * 16 + mr, hk * 2 + cl));
                b[2 * j][0] = r0;     b[2 * j][1] = r2;
                b[2 * j + 1][0] = r1; b[2 * j + 1][1] = r3;
            }
            #pragma unroll
            for (int i = 0; i < 4; i++)
                #pragma unroll
                for (int j = 0; j < 4; j++)
                    mma16816(acc[i][j], a[i], b[j]);
        }

        // issue next stage (single __syncthreads per iter is sufficient:
        // target buffer was last read at step s-1, before the sync above)
        if (s + STAGES - 1 < NSTEP) load_step(s + STAGES - 1);
        CPA_COMMIT();

        if (++kc == KSTEPS) {  // end of a q-pass: fold max, reset acc
            kc = 0;
            #pragma unroll
            for (int i = 0; i < 4; i++) {
                float m0 = cmax[i][0], m1 = cmax[i][1];
                #pragma unroll
                for (int j = 0; j < 4; j++) {
                    m0 = fmaxf(m0, fmaxf(acc[i][j][0], acc[i][j][1]));
                    m1 = fmaxf(m1, fmaxf(acc[i][j][2], acc[i][j][3]));
                    acc[i][j][0] = 0.f; acc[i][j][1] = 0.f;
                    acc[i][j][2] = 0.f; acc[i][j][3] = 0.f;
                }
                cmax[i][0] = m0; cmax[i][1] = m1;
            }
        }
    }

    // reduce max over quad lanes (columns live in lane&3)
    #pragma unroll
    for (int i = 0; i < 4; i++) {
        #pragma unroll
        for (int e = 0; e < 2; e++) {
            float v = cmax[i][e];
            v = fmaxf(v, __shfl_xor_sync(0xffffffffu, v, 1));
            v = fmaxf(v, __shfl_xor_sync(0xffffffffu, v, 2));
            cmax[i][e] = v;
        }
    }

    __syncthreads();  // tiles dead; reuse smem for cross-warp max
    float* red = (float*)smem;  // [4 warp_cols][128 rows]
    if ((lane & 3) == 0) {
        int base = (wid & 3) * 128 + wrow;
        int r = lane >> 2;  // 0..7
        #pragma unroll
        for (int i = 0; i < 4; i++) {
            red[base + i * 16 + r]     = cmax[i][0];
            red[base + i * 16 + r + 8] = cmax[i][1];
        }
    }
    __syncthreads();
    if (tid < 128) {
        float v = red[tid];
        v = fmaxf(v, red[128 + tid]);
        v = fmaxf(v, red[256 + tid]);
        v = fmaxf(v, red[384 + tid]);
        float d2 = fmaxf(2.0f - 2.0f * v, 0.0f);
        g_spatch[(size_t)pair * P + p0 + tid] = 0.5f * sqrtf(d2);
    }
}

// ---------------------------------------------------------------------------
// Kernel 3: scores[n] = mean_m max_p spatch; sp[n][p] = mean_m spatch.
// ---------------------------------------------------------------------------
__global__ void reduce_k(float* __restrict__ scores) {
    const int n = blockIdx.x;
    const int p = threadIdx.x;
    float v[8];
    float s = 0.f;
    #pragma unroll
    for (int m = 0; m < 8; m++) {
        v[m] = g_spatch[(size_t)(n * 8 + m) * P + p];
        s += v[m];
    }
    g_sp[n * P + p] = s * 0.125f;

    __shared__ int smax[8];
    if (p < 8) smax[p] = 0;  // dist >= 0 so int-compare == float-compare
    __syncthreads();
    #pragma unroll
    for (int m = 0; m < 8; m++) {
        float x = v[m];
        #pragma unroll
        for (int off = 16; off; off >>= 1)
            x = fmaxf(x, __shfl_xor_sync(0xffffffffu, x, off));
        if ((p & 31) == 0) atomicMax(&smax[m], __float_as_int(x));
    }
    __syncthreads();
    if (p == 0) {
        float t = 0.f;
        #pragma unroll
        for (int m = 0; m < 8; m++) t += __int_as_float(smax[m]);
        scores[n] = t * 0.125f;
    }
}

// ---------------------------------------------------------------------------
// Kernel 4: bilinear resize (8,32,32) -> (8,512,512)
// ---------------------------------------------------------------------------
__global__ void resize_k(float* __restrict__ out) {
    int idx = blockIdx.x * blockDim.x + threadIdx.x;
    if (idx >= N1 * OH * OW) return;
    int c = idx & (OW - 1);
    int r = (idx >> 9) & (OH - 1);
    int n = idx >> 18;
    float sy = (r + 0.5f) * ((float)PH / OH) - 0.5f;
    float sx = (c + 0.5f) * ((float)PW / OW) - 0.5f;
    float y0f = floorf(sy), x0f = floorf(sx);
    float wy = sy - y0f, wx = sx - x0f;
    int y0 = min(max((int)y0f, 0), PH - 1);
    int y1 = min(max((int)y0f + 1, 0), PH - 1);
    int x0 = min(max((int)x0f, 0), PW - 1);
    int x1 = min(max((int)x0f + 1, 0), PW - 1);
    const float* __restrict__ b = g_sp + n * (PH * PW);
    float v00 = b[y0 * PW + x0], v01 = b[y0 * PW + x1];
    float v10 = b[y1 * PW + x0], v11 = b[y1 * PW + x1];
    float top = v00 * (1.f - wx) + v01 * wx;
    float bot = v10 * (1.f - wx) + v11 * wx;
    out[idx] = top * (1.f - wy) + bot * wy;
}

// ---------------------------------------------------------------------------
extern "C" void kernel_launch(void* const* d_in, const int* in_sizes, int n_in,
                              void* d_out, int out_size) {
    (void)in_sizes; (void)n_in; (void)out_size;
    const float* feats  = (const float*)d_in[0];
    const float* nfeats = (const float*)d_in[1];
    float* out = (float*)d_out;  // [0..7] = scores, [8..] = scores_pixel

    cudaFuncSetAttribute(gemm_max_k,
                         cudaFuncAttributeMaxDynamicSharedMemorySize, SMEM_DYN);

    norm_k<<<(N1 + N2) * P, 192>>>(feats, nfeats);
    dim3 ggrid(P / BM, N1 * N2);
    gemm_max_k<<<ggrid, 256, SMEM_DYN>>>();
    reduce_k<<<N1, P>>>(out);
    resize_k<<<(N1 * OH * OW + 255) / 256, 256>>>(out + N1);
}

// round 8
// speedup vs baseline: 1.1291x; 1.1291x over previous
#include <cuda_runtime.h>
#include <cuda_bf16.h>
#include <math.h>
#include <stdint.h>

// Problem constants
#define N1 8
#define N2 8
#define P  1024
#define D  768
#define PH 32
#define PW 32
#define OH 512
#define OW 512

// GEMM tiling (mma.sync path; tcgen05 unavailable: harness targets sm_100 base)
#define BM 128
#define BN 128
#define BK 32
#define STAGES 3
#define KSTEPS (D / BK)           // 24
#define QSTEPS (P / BN)           // 8
#define NSTEP  (KSTEPS * QSTEPS)  // 192
#define TILE_BYTES  8192          // 128 rows * 32 bf16 * 2B
#define STAGE_BYTES (2 * TILE_BYTES)

#define NUNITS 512                // 8 p-blocks x 64 pairs
#define GRID_G 256                // persistent: 2 units per CTA, 1 balanced wave

// Scratch (no cudaMalloc allowed)
__device__ __nv_bfloat16 g_Fh[N1 * P * D];  // normalized feats, bf16
__device__ __nv_bfloat16 g_Gh[N2 * P * D];  // normalized nfeats, bf16
__device__ float g_spatch[N1 * N2 * P];     // scores_patch[n][m][p]
__device__ float g_sp[N1 * P];              // mean over m

// ---------------------------------------------------------------------------
// Helpers
// ---------------------------------------------------------------------------
__device__ __forceinline__ uint32_t cvta_s(const void* p) {
    return (uint32_t)__cvta_generic_to_shared(p);
}

#define CPA16(dst, src) \
    asm volatile("cp.async.cg.shared.global [%0], [%1], 16;\n" :: "r"(dst), "l"(src))
#define CPA_COMMIT()  asm volatile("cp.async.commit_group;\n" ::: "memory")
#define CPA_WAIT1()   asm volatile("cp.async.wait_group 1;\n" ::: "memory")
#define CPA_WAIT0()   asm volatile("cp.async.wait_group 0;\n" ::: "memory")

__device__ __forceinline__ void ldsm4(uint32_t& r0, uint32_t& r1, uint32_t& r2,
                                      uint32_t& r3, uint32_t a) {
    asm volatile("ldmatrix.sync.aligned.m8n8.x4.shared.b16 {%0,%1,%2,%3}, [%4];\n"
                 : "=r"(r0), "=r"(r1), "=r"(r2), "=r"(r3) : "r"(a));
}

__device__ __forceinline__ void mma16816(float* c, const uint32_t* a, const uint32_t* b) {
    asm volatile(
        "mma.sync.aligned.m16n8k16.row.col.f32.bf16.bf16.f32 "
        "{%0,%1,%2,%3}, {%4,%5,%6,%7}, {%8,%9}, {%0,%1,%2,%3};\n"
        : "+f"(c[0]), "+f"(c[1]), "+f"(c[2]), "+f"(c[3])
        : "r"(a[0]), "r"(a[1]), "r"(a[2]), "r"(a[3]), "r"(b[0]), "r"(b[1]));
}

// Tile row = 32 bf16 = 64B = 4 chunks of 16B. XOR swizzle: conflict-free
// ldmatrix (8 rows at fixed logical chunk hit 8 distinct 16B slots mod 128B).
__device__ __forceinline__ uint32_t swaddr(int row, int ch) {
    return (uint32_t)((row << 6) | (((ch ^ ((row >> 1) & 3)) & 3) << 4));
}

// ---------------------------------------------------------------------------
// Kernel 1: row-normalize -> bf16. grid = 16384 rows, block = 192
// ---------------------------------------------------------------------------
__global__ void norm_k(const float* __restrict__ feats,
                       const float* __restrict__ nfeats) {
    int row = blockIdx.x;
    const float* src;
    __nv_bfloat16* dst;
    if (row < N1 * P) {
        src = feats + (size_t)row * D;
        dst = g_Fh + (size_t)row * D;
    } else {
        int r = row - N1 * P;
        src = nfeats + (size_t)r * D;
        dst = g_Gh + (size_t)r * D;
    }
    int t = threadIdx.x;  // 0..191
    float4 x = *(const float4*)(src + t * 4);
    float s = x.x * x.x + x.y * x.y + x.z * x.z + x.w * x.w;
    #pragma unroll
    for (int off = 16; off; off >>= 1)
        s += __shfl_xor_sync(0xffffffffu, s, off);
    __shared__ float ws[6];
    __shared__ float rnorm_s;
    if ((t & 31) == 0) ws[t >> 5] = s;
    __syncthreads();
    if (t == 0) {
        float tot = 0.f;
        #pragma unroll
        for (int i = 0; i < 6; i++) tot += ws[i];
        rnorm_s = 1.0f / sqrtf(tot);
    }
    __syncthreads();
    float r = rnorm_s;
    __nv_bfloat162 h0 = __floats2bfloat162_rn(x.x * r, x.y * r);
    __nv_bfloat162 h1 = __floats2bfloat162_rn(x.z * r, x.w * r);
    uint2 pk;
    pk.x = *(uint32_t*)&h0;
    pk.y = *(uint32_t*)&h1;
    *(uint2*)(dst + t * 4) = pk;
}

// ---------------------------------------------------------------------------
// Kernel 2: bf16 tensor-core batched GEMM + running max over q.
// Persistent grid = 256 CTAs, each runs units 2b and 2b+1 (same pair ->
// B tiles L2-warm). 256 threads = 8 warps (2 m-rows x 4 n-cols), warp tile
// 64m x 32n, mma.m16n8k16, BK=32, 3-stage cp.async, loads issued early.
// ---------------------------------------------------------------------------
__global__ __launch_bounds__(256, 2)
void gemm_max_k() {
    __shared__ __align__(1024) unsigned char smem[STAGES * STAGE_BYTES];  // 48KB
    const uint32_t sbase = cvta_s(smem);

    const int tid  = threadIdx.x;
    const int lane = tid & 31;
    const int wid  = tid >> 5;
    const int wrow = (wid >> 2) * 64;  // warp m offset (0 / 64)
    const int wcol = (wid & 3) * 32;   // warp n offset (0..96)

    // loader mapping: thread -> (row = tid>>2 [+64], chunk = tid&3)
    const int lrow   = tid >> 2;  // 0..63
    const int lchunk = tid & 3;
    const uint32_t dA0 = swaddr(lrow, lchunk);
    const uint32_t dA1 = swaddr(lrow + 64, lchunk);

    // per-warp ldmatrix lane offsets
    const int mr = lane & 15;        // row-within-16 for ldsm
    const int cl = lane >> 4;        // 16B chunk select (0/1)

    for (int u = 0; u < 2; u++) {
        const int unit = blockIdx.x * 2 + u;   // 0..511
        const int pair = unit >> 3;
        const int p0   = (unit & 7) * BM;
        const __nv_bfloat16* __restrict__ Fb = g_Fh + (size_t)(pair >> 3) * P * D;
        const __nv_bfloat16* __restrict__ Gb = g_Gh + (size_t)(pair & 7) * P * D;

        float acc[4][4][4];
        float cmax[4][2];
        #pragma unroll
        for (int i = 0; i < 4; i++) { cmax[i][0] = -1e30f; cmax[i][1] = -1e30f; }
        #pragma unroll
        for (int i = 0; i < 4; i++)
            #pragma unroll
            for (int j = 0; j < 4; j++)
                #pragma unroll
                for (int e = 0; e < 4; e++) acc[i][j][e] = 0.f;

        auto load_step = [&](int s) {
            int q0 = (s / KSTEPS) * BN;
            int k0 = (s % KSTEPS) * BK;
            uint32_t Ab = sbase + (s % STAGES) * STAGE_BYTES;
            uint32_t Bb = Ab + TILE_BYTES;
            int ke = k0 + lchunk * 8;
            CPA16(Ab + dA0, Fb + ((size_t)(p0 + lrow) * D + ke));
            CPA16(Ab + dA1, Fb + ((size_t)(p0 + lrow + 64) * D + ke));
            CPA16(Bb + dA0, Gb + ((size_t)(q0 + lrow) * D + ke));
            CPA16(Bb + dA1, Gb + ((size_t)(q0 + lrow + 64) * D + ke));
        };

        // prologue
        #pragma unroll
        for (int s = 0; s < STAGES - 1; s++) {
            load_step(s);
            CPA_COMMIT();
        }

        int kc = 0;  // position within current q-pass
        for (int s = 0; s < NSTEP; s++) {
            CPA_WAIT1();
            __syncthreads();

            // issue s+2 loads EARLY: stage (s+2)%3 was last read at iter s-1,
            // retired before the barrier above; overlap with the MMA burst.
            if (s + STAGES - 1 < NSTEP) load_step(s + STAGES - 1);
            CPA_COMMIT();

            uint32_t Ab = sbase + (s % STAGES) * STAGE_BYTES;
            uint32_t Bb = Ab + TILE_BYTES;

            #pragma unroll
            for (int hk = 0; hk < 2; hk++) {
                uint32_t a[4][4], b[4][2];
                #pragma unroll
                for (int i = 0; i < 4; i++)
                    ldsm4(a[i][0], a[i][1], a[i][2], a[i][3],
                          Ab + swaddr(wrow + i * 16 + mr, hk * 2 + cl));
                #pragma unroll
                for (int j = 0; j < 2; j++) {
                    uint32_t r0, r1, r2, r3;
                    ldsm4(r0, r1, r2, r3,
                          Bb + swaddr(wcol + j * 16 + mr, hk * 2 + cl));
                    b[2 * j][0] = r0;     b[2 * j][1] = r2;
                    b[2 * j + 1][0] = r1; b[2 * j + 1][1] = r3;
                }
                #pragma unroll
                for (int i = 0; i < 4; i++)
                    #pragma unroll
                    for (int j = 0; j < 4; j++)
                        mma16816(acc[i][j], a[i], b[j]);
            }

            if (++kc == KSTEPS) {  // end of a q-pass: fold max, reset acc
                kc = 0;
                #pragma unroll
                for (int i = 0; i < 4; i++) {
                    float m0 = cmax[i][0], m1 = cmax[i][1];
                    #pragma unroll
                    for (int j = 0; j < 4; j++) {
                        m0 = fmaxf(m0, fmaxf(acc[i][j][0], acc[i][j][1]));
                        m1 = fmaxf(m1, fmaxf(acc[i][j][2], acc[i][j][3]));
                        acc[i][j][0] = 0.f; acc[i][j][1] = 0.f;
                        acc[i][j][2] = 0.f; acc[i][j][3] = 0.f;
                    }
                    cmax[i][0] = m0; cmax[i][1] = m1;
                }
            }
        }
        CPA_WAIT0();  // drain pipeline before smem reuse

        // reduce max over quad lanes (columns live in lane&3)
        #pragma unroll
        for (int i = 0; i < 4; i++) {
            #pragma unroll
            for (int e = 0; e < 2; e++) {
                float v = cmax[i][e];
                v = fmaxf(v, __shfl_xor_sync(0xffffffffu, v, 1));
                v = fmaxf(v, __shfl_xor_sync(0xffffffffu, v, 2));
                cmax[i][e] = v;
            }
        }

        __syncthreads();  // tiles dead; reuse smem for cross-warp max
        float* red = (float*)smem;  // [4 warp_cols][128 rows]
        if ((lane & 3) == 0) {
            int base = (wid & 3) * 128 + wrow;
            int r = lane >> 2;  // 0..7
            #pragma unroll
            for (int i = 0; i < 4; i++) {
                red[base + i * 16 + r]     = cmax[i][0];
                red[base + i * 16 + r + 8] = cmax[i][1];
            }
        }
        __syncthreads();
        if (tid < 128) {
            float v = red[tid];
            v = fmaxf(v, red[128 + tid]);
            v = fmaxf(v, red[256 + tid]);
            v = fmaxf(v, red[384 + tid]);
            float d2 = fmaxf(2.0f - 2.0f * v, 0.0f);
            g_spatch[(size_t)pair * P + p0 + tid] = 0.5f * sqrtf(d2);
        }
        __syncthreads();  // reduction reads done before next unit's cp.async
    }
}

// ---------------------------------------------------------------------------
// Kernel 3: scores[n] = mean_m max_p spatch; sp[n][p] = mean_m spatch.
// ---------------------------------------------------------------------------
__global__ void reduce_k(float* __restrict__ scores) {
    const int n = blockIdx.x;
    const int p = threadIdx.x;
    float v[8];
    float s = 0.f;
    #pragma unroll
    for (int m = 0; m < 8; m++) {
        v[m] = g_spatch[(size_t)(n * 8 + m) * P + p];
        s += v[m];
    }
    g_sp[n * P + p] = s * 0.125f;

    __shared__ int smax[8];
    if (p < 8) smax[p] = 0;  // dist >= 0 so int-compare == float-compare
    __syncthreads();
    #pragma unroll
    for (int m = 0; m < 8; m++) {
        float x = v[m];
        #pragma unroll
        for (int off = 16; off; off >>= 1)
            x = fmaxf(x, __shfl_xor_sync(0xffffffffu, x, off));
        if ((p & 31) == 0) atomicMax(&smax[m], __float_as_int(x));
    }
    __syncthreads();
    if (p == 0) {
        float t = 0.f;
        #pragma unroll
        for (int m = 0; m < 8; m++) t += __int_as_float(smax[m]);
        scores[n] = t * 0.125f;
    }
}

// ---------------------------------------------------------------------------
// Kernel 4: bilinear resize (8,32,32) -> (8,512,512)
// ---------------------------------------------------------------------------
__global__ void resize_k(float* __restrict__ out) {
    int idx = blockIdx.x * blockDim.x + threadIdx.x;
    if (idx >= N1 * OH * OW) return;
    int c = idx & (OW - 1);
    int r = (idx >> 9) & (OH - 1);
    int n = idx >> 18;
    float sy = (r + 0.5f) * ((float)PH / OH) - 0.5f;
    float sx = (c + 0.5f) * ((float)PW / OW) - 0.5f;
    float y0f = floorf(sy), x0f = floorf(sx);
    float wy = sy - y0f, wx = sx - x0f;
    int y0 = min(max((int)y0f, 0), PH - 1);
    int y1 = min(max((int)y0f + 1, 0), PH - 1);
    int x0 = min(max((int)x0f, 0), PW - 1);
    int x1 = min(max((int)x0f + 1, 0), PW - 1);
    const float* __restrict__ b = g_sp + n * (PH * PW);
    float v00 = b[y0 * PW + x0], v01 = b[y0 * PW + x1];
    float v10 = b[y1 * PW + x0], v11 = b[y1 * PW + x1];
    float top = v00 * (1.f - wx) + v01 * wx;
    float bot = v10 * (1.f - wx) + v11 * wx;
    out[idx] = top * (1.f - wy) + bot * wy;
}

// ---------------------------------------------------------------------------
extern "C" void kernel_launch(void* const* d_in, const int* in_sizes, int n_in,
                              void* d_out, int out_size) {
    (void)in_sizes; (void)n_in; (void)out_size;
    const float* feats  = (const float*)d_in[0];
    const float* nfeats = (const float*)d_in[1];
    float* out = (float*)d_out;  // [0..7] = scores, [8..] = scores_pixel

    norm_k<<<(N1 + N2) * P, 192>>>(feats, nfeats);
    gemm_max_k<<<GRID_G, 256>>>();
    reduce_k<<<N1, P>>>(out);
    resize_k<<<(N1 * OH * OW + 255) / 256, 256>>>(out + N1);
}

// round 9
// speedup vs baseline: 1.1968x; 1.0599x over previous
#include <cuda_runtime.h>
#include <cuda_bf16.h>
#include <math.h>
#include <stdint.h>

// Problem constants
#define N1 8
#define N2 8
#define P  1024
#define D  768
#define PH 32
#define PW 32
#define OH 512
#define OW 512

// GEMM tiling (mma.sync path; tcgen05 unavailable: harness targets sm_100 base)
#define BM 128
#define BN 128
#define BK 32
#define STAGES 3
#define KSTEPS (D / BK)           // 24
#define QSTEPS (P / BN)           // 8
#define NSTEP  (KSTEPS * QSTEPS)  // 192
#define TILE_BYTES  8192          // 128 rows * 32 bf16 * 2B
#define STAGE_BYTES (2 * TILE_BYTES)

// Scratch (no cudaMalloc allowed)
__device__ __nv_bfloat16 g_Fh[N1 * P * D];  // normalized feats, bf16
__device__ __nv_bfloat16 g_Gh[N2 * P * D];  // normalized nfeats, bf16
__device__ float g_spatch[N1 * N2 * P];     // scores_patch[n][m][p]
__device__ float g_sp[N1 * P];              // mean over m

// ---------------------------------------------------------------------------
// Helpers
// ---------------------------------------------------------------------------
__device__ __forceinline__ uint32_t cvta_s(const void* p) {
    return (uint32_t)__cvta_generic_to_shared(p);
}

#define CPA16(dst, src) \
    asm volatile("cp.async.cg.shared.global [%0], [%1], 16;\n" :: "r"(dst), "l"(src))
#define CPA_COMMIT()  asm volatile("cp.async.commit_group;\n" ::: "memory")
#define CPA_WAIT1()   asm volatile("cp.async.wait_group 1;\n" ::: "memory")

__device__ __forceinline__ void ldsm4(uint32_t& r0, uint32_t& r1, uint32_t& r2,
                                      uint32_t& r3, uint32_t a) {
    asm volatile("ldmatrix.sync.aligned.m8n8.x4.shared.b16 {%0,%1,%2,%3}, [%4];\n"
                 : "=r"(r0), "=r"(r1), "=r"(r2), "=r"(r3) : "r"(a));
}

__device__ __forceinline__ void mma16816(float* c, const uint32_t* a, const uint32_t* b) {
    asm volatile(
        "mma.sync.aligned.m16n8k16.row.col.f32.bf16.bf16.f32 "
        "{%0,%1,%2,%3}, {%4,%5,%6,%7}, {%8,%9}, {%0,%1,%2,%3};\n"
        : "+f"(c[0]), "+f"(c[1]), "+f"(c[2]), "+f"(c[3])
        : "r"(a[0]), "r"(a[1]), "r"(a[2]), "r"(a[3]), "r"(b[0]), "r"(b[1]));
}

// Tile row = 32 bf16 = 64B = 4 chunks of 16B. XOR swizzle: conflict-free
// ldmatrix (8 rows at fixed logical chunk hit 8 distinct 16B slots mod 128B).
__device__ __forceinline__ uint32_t swaddr(int row, int ch) {
    return (uint32_t)((row << 6) | (((ch ^ ((row >> 1) & 3)) & 3) << 4));
}

// ---------------------------------------------------------------------------
// Kernel 1: row-normalize -> bf16. grid = 16384 rows, block = 192
// ---------------------------------------------------------------------------
__global__ void norm_k(const float* __restrict__ feats,
                       const float* __restrict__ nfeats) {
    int row = blockIdx.x;
    const float* src;
    __nv_bfloat16* dst;
    if (row < N1 * P) {
        src = feats + (size_t)row * D;
        dst = g_Fh + (size_t)row * D;
    } else {
        int r = row - N1 * P;
        src = nfeats + (size_t)r * D;
        dst = g_Gh + (size_t)r * D;
    }
    int t = threadIdx.x;  // 0..191
    float4 x = *(const float4*)(src + t * 4);
    float s = x.x * x.x + x.y * x.y + x.z * x.z + x.w * x.w;
    #pragma unroll
    for (int off = 16; off; off >>= 1)
        s += __shfl_xor_sync(0xffffffffu, s, off);
    __shared__ float ws[6];
    __shared__ float rnorm_s;
    if ((t & 31) == 0) ws[t >> 5] = s;
    __syncthreads();
    if (t == 0) {
        float tot = 0.f;
        #pragma unroll
        for (int i = 0; i < 6; i++) tot += ws[i];
        rnorm_s = 1.0f / sqrtf(tot);
    }
    __syncthreads();
    float r = rnorm_s;
    __nv_bfloat162 h0 = __floats2bfloat162_rn(x.x * r, x.y * r);
    __nv_bfloat162 h1 = __floats2bfloat162_rn(x.z * r, x.w * r);
    uint2 pk;
    pk.x = *(uint32_t*)&h0;
    pk.y = *(uint32_t*)&h1;
    *(uint2*)(dst + t * 4) = pk;
}

// ---------------------------------------------------------------------------
// Kernel 2: bf16 tensor-core batched GEMM + running max over q.
// grid = (P/BM = 8, 64 pairs), 128 threads = 4 warps (2x2), warp tile
// 64m x 64n (mma:ldsm issue ratio 4:1 vs 2.7:1 before), BK=32, 3-stage
// cp.async pipeline. Loads issued after MMA burst (R5 ordering).
// ---------------------------------------------------------------------------
__global__ __launch_bounds__(128, 2)
void gemm_max_k() {
    __shared__ __align__(1024) unsigned char smem[STAGES * STAGE_BYTES];  // 48KB
    const uint32_t sbase = cvta_s(smem);

    const int pair = blockIdx.y;
    const __nv_bfloat16* __restrict__ Fb = g_Fh + (size_t)(pair >> 3) * P * D;
    const __nv_bfloat16* __restrict__ Gb = g_Gh + (size_t)(pair & 7) * P * D;
    const int p0 = blockIdx.x * BM;

    const int tid  = threadIdx.x;
    const int lane = tid & 31;
    const int wid  = tid >> 5;          // 0..3
    const int wrow = (wid >> 1) * 64;   // warp m offset (0 / 64)
    const int wcol = (wid & 1) * 64;    // warp n offset (0 / 64)

    // loader mapping (same coalescing as R5): 4 lanes cover one row's 4 chunks,
    // warp covers 8 consecutive rows; 4 passes of 32 rows each.
    const int lrow   = tid >> 2;  // 0..31
    const int lchunk = tid & 3;

    float acc[4][8][4];
    float cmax[4][2];
    #pragma unroll
    for (int i = 0; i < 4; i++) { cmax[i][0] = -1e30f; cmax[i][1] = -1e30f; }
    #pragma unroll
    for (int i = 0; i < 4; i++)
        #pragma unroll
        for (int j = 0; j < 8; j++)
            #pragma unroll
            for (int e = 0; e < 4; e++) acc[i][j][e] = 0.f;

    // -------- cp.async tile loader for flattened step s --------
    auto load_step = [&](int s) {
        int q0 = (s / KSTEPS) * BN;
        int k0 = (s % KSTEPS) * BK;
        uint32_t Ab = sbase + (s % STAGES) * STAGE_BYTES;
        uint32_t Bb = Ab + TILE_BYTES;
        int ke = k0 + lchunk * 8;
        #pragma unroll
        for (int ps = 0; ps < 4; ps++) {
            int r = lrow + ps * 32;
            uint32_t d = swaddr(r, lchunk);
            CPA16(Ab + d, Fb + ((size_t)(p0 + r) * D + ke));
            CPA16(Bb + d, Gb + ((size_t)(q0 + r) * D + ke));
        }
    };

    // prologue
    #pragma unroll
    for (int s = 0; s < STAGES - 1; s++) {
        load_step(s);
        CPA_COMMIT();
    }

    // per-warp ldmatrix lane offsets
    const int mr = lane & 15;        // row-within-16 for ldsm
    const int cl = lane >> 4;        // 16B chunk select (0/1)

    int kc = 0;  // position within current q-pass
    for (int s = 0; s < NSTEP; s++) {
        CPA_WAIT1();
        __syncthreads();
        uint32_t Ab = sbase + (s % STAGES) * STAGE_BYTES;
        uint32_t Bb = Ab + TILE_BYTES;

        #pragma unroll
        for (int hk = 0; hk < 2; hk++) {
            uint32_t a[4][4], b[8][2];
            #pragma unroll
            for (int i = 0; i < 4; i++)
                ldsm4(a[i][0], a[i][1], a[i][2], a[i][3],
                      Ab + swaddr(wrow + i * 16 + mr, hk * 2 + cl));
            #pragma unroll
            for (int j = 0; j < 4; j++) {
                uint32_t r0, r1, r2, r3;
                ldsm4(r0, r1, r2, r3,
                      Bb + swaddr(wcol + j * 16 + mr, hk * 2 + cl));
                b[2 * j][0] = r0;     b[2 * j][1] = r2;
                b[2 * j + 1][0] = r1; b[2 * j + 1][1] = r3;
            }
            #pragma unroll
            for (int i = 0; i < 4; i++)
                #pragma unroll
                for (int j = 0; j < 8; j++)
                    mma16816(acc[i][j], a[i], b[j]);
        }

        // issue next stage (R5 ordering: after MMA burst)
        if (s + STAGES - 1 < NSTEP) load_step(s + STAGES - 1);
        CPA_COMMIT();

        if (++kc == KSTEPS) {  // end of a q-pass: fold max, reset acc
            kc = 0;
            #pragma unroll
            for (int i = 0; i < 4; i++) {
                float m0 = cmax[i][0], m1 = cmax[i][1];
                #pragma unroll
                for (int j = 0; j < 8; j++) {
                    m0 = fmaxf(m0, fmaxf(acc[i][j][0], acc[i][j][1]));
                    m1 = fmaxf(m1, fmaxf(acc[i][j][2], acc[i][j][3]));
                    acc[i][j][0] = 0.f; acc[i][j][1] = 0.f;
                    acc[i][j][2] = 0.f; acc[i][j][3] = 0.f;
                }
                cmax[i][0] = m0; cmax[i][1] = m1;
            }
        }
    }

    // reduce max over quad lanes (columns live in lane&3)
    #pragma unroll
    for (int i = 0; i < 4; i++) {
        #pragma unroll
        for (int e = 0; e < 2; e++) {
            float v = cmax[i][e];
            v = fmaxf(v, __shfl_xor_sync(0xffffffffu, v, 1));
            v = fmaxf(v, __shfl_xor_sync(0xffffffffu, v, 2));
            cmax[i][e] = v;
        }
    }

    __syncthreads();  // tiles dead; reuse smem for cross-warp max
    float* red = (float*)smem;  // [2 warp_cols][128 rows]
    if ((lane & 3) == 0) {
        int base = (wid & 1) * 128 + wrow;
        int r = lane >> 2;  // 0..7
        #pragma unroll
        for (int i = 0; i < 4; i++) {
            red[base + i * 16 + r]     = cmax[i][0];
            red[base + i * 16 + r + 8] = cmax[i][1];
        }
    }
    __syncthreads();
    {
        float v = fmaxf(red[tid], red[128 + tid]);
        float d2 = fmaxf(2.0f - 2.0f * v, 0.0f);
        g_spatch[(size_t)pair * P + p0 + tid] = 0.5f * sqrtf(d2);
    }
}

// ---------------------------------------------------------------------------
// Kernel 3: scores[n] = mean_m max_p spatch; sp[n][p] = mean_m spatch.
// ---------------------------------------------------------------------------
__global__ void reduce_k(float* __restrict__ scores) {
    const int n = blockIdx.x;
    const int p = threadIdx.x;
    float v[8];
    float s = 0.f;
    #pragma unroll
    for (int m = 0; m < 8; m++) {
        v[m] = g_spatch[(size_t)(n * 8 + m) * P + p];
        s += v[m];
    }
    g_sp[n * P + p] = s * 0.125f;

    __shared__ int smax[8];
    if (p < 8) smax[p] = 0;  // dist >= 0 so int-compare == float-compare
    __syncthreads();
    #pragma unroll
    for (int m = 0; m < 8; m++) {
        float x = v[m];
        #pragma unroll
        for (int off = 16; off; off >>= 1)
            x = fmaxf(x, __shfl_xor_sync(0xffffffffu, x, off));
        if ((p & 31) == 0) atomicMax(&smax[m], __float_as_int(x));
    }
    __syncthreads();
    if (p == 0) {
        float t = 0.f;
        #pragma unroll
        for (int m = 0; m < 8; m++) t += __int_as_float(smax[m]);
        scores[n] = t * 0.125f;
    }
}

// ---------------------------------------------------------------------------
// Kernel 4: bilinear resize (8,32,32) -> (8,512,512)
// ---------------------------------------------------------------------------
__global__ void resize_k(float* __restrict__ out) {
    int idx = blockIdx.x * blockDim.x + threadIdx.x;
    if (idx >= N1 * OH * OW) return;
    int c = idx & (OW - 1);
    int r = (idx >> 9) & (OH - 1);
    int n = idx >> 18;
    float sy = (r + 0.5f) * ((float)PH / OH) - 0.5f;
    float sx = (c + 0.5f) * ((float)PW / OW) - 0.5f;
    float y0f = floorf(sy), x0f = floorf(sx);
    float wy = sy - y0f, wx = sx - x0f;
    int y0 = min(max((int)y0f, 0), PH - 1);
    int y1 = min(max((int)y0f + 1, 0), PH - 1);
    int x0 = min(max((int)x0f, 0), PW - 1);
    int x1 = min(max((int)x0f + 1, 0), PW - 1);
    const float* __restrict__ b = g_sp + n * (PH * PW);
    float v00 = b[y0 * PW + x0], v01 = b[y0 * PW + x1];
    float v10 = b[y1 * PW + x0], v11 = b[y1 * PW + x1];
    float top = v00 * (1.f - wx) + v01 * wx;
    float bot = v10 * (1.f - wx) + v11 * wx;
    out[idx] = top * (1.f - wy) + bot * wy;
}

// ---------------------------------------------------------------------------
extern "C" void kernel_launch(void* const* d_in, const int* in_sizes, int n_in,
                              void* d_out, int out_size) {
    (void)in_sizes; (void)n_in; (void)out_size;
    const float* feats  = (const float*)d_in[0];
    const float* nfeats = (const float*)d_in[1];
    float* out = (float*)d_out;  // [0..7] = scores, [8..] = scores_pixel

    norm_k<<<(N1 + N2) * P, 192>>>(feats, nfeats);
    dim3 ggrid(P / BM, N1 * N2);
    gemm_max_k<<<ggrid, 128>>>();
    reduce_k<<<N1, P>>>(out);
    resize_k<<<(N1 * OH * OW + 255) / 256, 256>>>(out + N1);
}

// round 10
// speedup vs baseline: 2.0942x; 1.7499x over previous
#include <cuda_runtime.h>
#include <cuda_bf16.h>
#include <math.h>
#include <stdint.h>

// Problem constants
#define N1 8
#define N2 8
#define P  1024
#define D  768
#define PH 32
#define PW 32
#define OH 512
#define OW 512

// GEMM tiling — INT8 IMMA path (mma.sync m16n8k32.s8).
// tcgen05 unavailable (harness targets sm_100 base).
#define BM 128
#define BN 128
#define BK 64                     // 64 int8 = 64B per tile row (same bytes as R5)
#define STAGES 3
#define KSTEPS (D / BK)           // 12
#define QSTEPS (P / BN)           // 8
#define NSTEP  (KSTEPS * QSTEPS)  // 96
#define TILE_BYTES  8192          // 128 rows * 64 B
#define STAGE_BYTES (2 * TILE_BYTES)
#define SMEM_TILES  (STAGES * STAGE_BYTES)   // 49152
#define SMEM_SBV    SMEM_TILES               // 128 floats of B scales
#define SMEM_DYN    (SMEM_TILES + 512)

// Scratch (no cudaMalloc allowed)
__device__ int8_t g_Fq[N1 * P * D];   // normalized feats, int8 (per-row scaled)
__device__ int8_t g_Gq[N2 * P * D];   // normalized nfeats, int8
__device__ float  g_sF[N1 * P];       // per-row scales for F
__device__ float  g_sG[N2 * P];       // per-row scales for G
__device__ float  g_spatch[N1 * N2 * P];
__device__ float  g_sp[N1 * P];

// ---------------------------------------------------------------------------
// Helpers
// ---------------------------------------------------------------------------
__device__ __forceinline__ uint32_t cvta_s(const void* p) {
    return (uint32_t)__cvta_generic_to_shared(p);
}

#define CPA16(dst, src) \
    asm volatile("cp.async.cg.shared.global [%0], [%1], 16;\n" :: "r"(dst), "l"(src))
#define CPA_COMMIT()  asm volatile("cp.async.commit_group;\n" ::: "memory")
#define CPA_WAIT1()   asm volatile("cp.async.wait_group 1;\n" ::: "memory")

__device__ __forceinline__ void ldsm4(uint32_t& r0, uint32_t& r1, uint32_t& r2,
                                      uint32_t& r3, uint32_t a) {
    asm volatile("ldmatrix.sync.aligned.m8n8.x4.shared.b16 {%0,%1,%2,%3}, [%4];\n"
                 : "=r"(r0), "=r"(r1), "=r"(r2), "=r"(r3) : "r"(a));
}

__device__ __forceinline__ void mma16832s8(int* c, const uint32_t* a,
                                           const uint32_t* b) {
    asm volatile(
        "mma.sync.aligned.m16n8k32.row.col.s32.s8.s8.s32 "
        "{%0,%1,%2,%3}, {%4,%5,%6,%7}, {%8,%9}, {%0,%1,%2,%3};\n"
        : "+r"(c[0]), "+r"(c[1]), "+r"(c[2]), "+r"(c[3])
        : "r"(a[0]), "r"(a[1]), "r"(a[2]), "r"(a[3]), "r"(b[0]), "r"(b[1]));
}

// Tile row = 64 int8 = 64B = 4 chunks of 16B. Same XOR swizzle as R5:
// 8 rows at a fixed logical chunk hit 8 distinct 16B slots mod 128B.
__device__ __forceinline__ uint32_t swaddr(int row, int ch) {
    return (uint32_t)((row << 6) | (((ch ^ ((row >> 1) & 3)) & 3) << 4));
}

// ---------------------------------------------------------------------------
// Kernel 1: row-normalize -> per-row-scaled int8. grid = 16384 rows, block 192
// ---------------------------------------------------------------------------
__global__ void norm_k(const float* __restrict__ feats,
                       const float* __restrict__ nfeats) {
    int row = blockIdx.x;
    const float* src;
    int8_t* dst;
    float* sdst;
    int srow;
    if (row < N1 * P) {
        src = feats + (size_t)row * D;
        dst = g_Fq + (size_t)row * D;
        sdst = g_sF; srow = row;
    } else {
        int r = row - N1 * P;
        src = nfeats + (size_t)r * D;
        dst = g_Gq + (size_t)r * D;
        sdst = g_sG; srow = r;
    }
    int t = threadIdx.x;  // 0..191
    float4 x = *(const float4*)(src + t * 4);
    float s = x.x * x.x + x.y * x.y + x.z * x.z + x.w * x.w;
    #pragma unroll
    for (int off = 16; off; off >>= 1)
        s += __shfl_xor_sync(0xffffffffu, s, off);
    __shared__ float ws[6];
    __shared__ float rnorm_s, amax_s;
    if ((t & 31) == 0) ws[t >> 5] = s;
    __syncthreads();
    if (t == 0) {
        float tot = 0.f;
        #pragma unroll
        for (int i = 0; i < 6; i++) tot += ws[i];
        rnorm_s = 1.0f / sqrtf(tot);
    }
    __syncthreads();
    float r = rnorm_s;
    float y0 = x.x * r, y1 = x.y * r, y2 = x.z * r, y3 = x.w * r;

    // block max of |y|
    float am = fmaxf(fmaxf(fabsf(y0), fabsf(y1)), fmaxf(fabsf(y2), fabsf(y3)));
    #pragma unroll
    for (int off = 16; off; off >>= 1)
        am = fmaxf(am, __shfl_xor_sync(0xffffffffu, am, off));
    if ((t & 31) == 0) ws[t >> 5] = am;
    __syncthreads();
    if (t == 0) {
        float mx = 0.f;
        #pragma unroll
        for (int i = 0; i < 6; i++) mx = fmaxf(mx, ws[i]);
        amax_s = mx;
        sdst[srow] = mx * (1.0f / 127.0f);
    }
    __syncthreads();
    float scale = 127.0f / amax_s;
    int q0 = __float2int_rn(y0 * scale);
    int q1 = __float2int_rn(y1 * scale);
    int q2 = __float2int_rn(y2 * scale);
    int q3 = __float2int_rn(y3 * scale);
    uint32_t pk = (uint32_t)(q0 & 0xff) | ((uint32_t)(q1 & 0xff) << 8) |
                  ((uint32_t)(q2 & 0xff) << 16) | ((uint32_t)(q3 & 0xff) << 24);
    *(uint32_t*)(dst + t * 4) = pk;
}

// ---------------------------------------------------------------------------
// Kernel 2: int8 tensor-core batched GEMM + running (scaled) max over q.
// grid = (P/BM = 8, 64 pairs), 256 threads = 8 warps (2 m-rows x 4 n-cols),
// warp tile 64m x 32n, mma.m16n8k32.s8, BK=64, 3-stage cp.async pipeline.
// Identical loader/swizzle/ldsm structure to the R5 bf16 kernel (fragment
// bytes per thread are byte-identical between bf16-k16 and s8-k32).
// ---------------------------------------------------------------------------
__global__ __launch_bounds__(256, 2)
void gemm_max_k() {
    extern __shared__ __align__(1024) unsigned char smem[];
    const uint32_t sbase = cvta_s(smem);
    float* sbv = (float*)(smem + SMEM_SBV);  // B scales for current q-pass

    const int pair = blockIdx.y;
    const int8_t* __restrict__ Fb = g_Fq + (size_t)(pair >> 3) * P * D;
    const int8_t* __restrict__ Gb = g_Gq + (size_t)(pair & 7) * P * D;
    const float* __restrict__ sFp = g_sF + (size_t)(pair >> 3) * P;
    const float* __restrict__ sGp = g_sG + (size_t)(pair & 7) * P;
    const int p0 = blockIdx.x * BM;

    const int tid  = threadIdx.x;
    const int lane = tid & 31;
    const int wid  = tid >> 5;
    const int wrow = (wid >> 2) * 64;  // warp m offset (0 / 64)
    const int wcol = (wid & 3) * 32;   // warp n offset (0..96)

    // loader mapping: thread -> (row = tid>>2 [+64], chunk = tid&3)
    const int lrow   = tid >> 2;  // 0..63
    const int lchunk = tid & 3;
    const uint32_t dA0 = swaddr(lrow, lchunk);
    const uint32_t dA1 = swaddr(lrow + 64, lchunk);

    int acc[4][4][4];
    float cmax[4][2];
    #pragma unroll
    for (int i = 0; i < 4; i++) { cmax[i][0] = -1e30f; cmax[i][1] = -1e30f; }
    #pragma unroll
    for (int i = 0; i < 4; i++)
        #pragma unroll
        for (int j = 0; j < 4; j++)
            #pragma unroll
            for (int e = 0; e < 4; e++) acc[i][j][e] = 0;

    // -------- cp.async tile loader for flattened step s --------
    auto load_step = [&](int s) {
        int q0 = (s / KSTEPS) * BN;
        int k0 = (s % KSTEPS) * BK;
        uint32_t Ab = sbase + (s % STAGES) * STAGE_BYTES;
        uint32_t Bb = Ab + TILE_BYTES;
        int ke = k0 + lchunk * 16;  // int8 elements
        CPA16(Ab + dA0, Fb + ((size_t)(p0 + lrow) * D + ke));
        CPA16(Ab + dA1, Fb + ((size_t)(p0 + lrow + 64) * D + ke));
        CPA16(Bb + dA0, Gb + ((size_t)(q0 + lrow) * D + ke));
        CPA16(Bb + dA1, Gb + ((size_t)(q0 + lrow + 64) * D + ke));
    };

    // prologue
    #pragma unroll
    for (int s = 0; s < STAGES - 1; s++) {
        load_step(s);
        CPA_COMMIT();
    }

    // per-warp ldmatrix lane offsets
    const int mr = lane & 15;        // row-within-16 for ldsm
    const int cl = lane >> 4;        // 16B chunk select (0/1)
    const int qb = wcol + 2 * (lane & 3);  // this lane's base q col in tile

    int kc = 0;  // position within current q-pass
    for (int s = 0; s < NSTEP; s++) {
        CPA_WAIT1();
        __syncthreads();

        // q-pass start: stage B scales for the fold (visible via later syncs)
        if (kc == 0 && tid < 128) sbv[tid] = sGp[(s / KSTEPS) * BN + tid];

        uint32_t Ab = sbase + (s % STAGES) * STAGE_BYTES;
        uint32_t Bb = Ab + TILE_BYTES;

        #pragma unroll
        for (int hk = 0; hk < 2; hk++) {  // two k32 groups in BK=64
            uint32_t a[4][4], b[4][2];
            #pragma unroll
            for (int i = 0; i < 4; i++)
                ldsm4(a[i][0], a[i][1], a[i][2], a[i][3],
                      Ab + swaddr(wrow + i * 16 + mr, hk * 2 + cl));
            #pragma unroll
            for (int j = 0; j < 2; j++) {
                uint32_t r0, r1, r2, r3;
                ldsm4(r0, r1, r2, r3,
                      Bb + swaddr(wcol + j * 16 + mr, hk * 2 + cl));
                b[2 * j][0] = r0;     b[2 * j][1] = r2;
                b[2 * j + 1][0] = r1; b[2 * j + 1][1] = r3;
            }
            #pragma unroll
            for (int i = 0; i < 4; i++)
                #pragma unroll
                for (int j = 0; j < 4; j++)
                    mma16832s8(acc[i][j], a[i], b[j]);
        }

        // issue next stage (R5 ordering: after MMA burst)
        if (s + STAGES - 1 < NSTEP) load_step(s + STAGES - 1);
        CPA_COMMIT();

        if (++kc == KSTEPS) {  // end of a q-pass: scale by sb[q], fold max
            kc = 0;
            #pragma unroll
            for (int i = 0; i < 4; i++) {
                float m0 = cmax[i][0], m1 = cmax[i][1];
                #pragma unroll
                for (int j = 0; j < 4; j++) {
                    float s0 = sbv[qb + j * 8];
                    float s1 = sbv[qb + j * 8 + 1];
                    m0 = fmaxf(m0, fmaxf((float)acc[i][j][0] * s0,
                                         (float)acc[i][j][1] * s1));
                    m1 = fmaxf(m1, fmaxf((float)acc[i][j][2] * s0,
                                         (float)acc[i][j][3] * s1));
                    acc[i][j][0] = 0; acc[i][j][1] = 0;
                    acc[i][j][2] = 0; acc[i][j][3] = 0;
                }
                cmax[i][0] = m0; cmax[i][1] = m1;
            }
        }
    }

    // reduce max over quad lanes (columns live in lane&3; sb already applied)
    #pragma unroll
    for (int i = 0; i < 4; i++) {
        #pragma unroll
        for (int e = 0; e < 2; e++) {
            float v = cmax[i][e];
            v = fmaxf(v, __shfl_xor_sync(0xffffffffu, v, 1));
            v = fmaxf(v, __shfl_xor_sync(0xffffffffu, v, 2));
            cmax[i][e] = v;
        }
    }

    __syncthreads();  // tiles dead; reuse smem for cross-warp max
    float* red = (float*)smem;  // [4 warp_cols][128 rows]
    if ((lane & 3) == 0) {
        int base = (wid & 3) * 128 + wrow;
        int r = lane >> 2;  // 0..7
        #pragma unroll
        for (int i = 0; i < 4; i++) {
            red[base + i * 16 + r]     = cmax[i][0];
            red[base + i * 16 + r + 8] = cmax[i][1];
        }
    }
    __syncthreads();
    if (tid < 128) {
        float v = red[tid];
        v = fmaxf(v, red[128 + tid]);
        v = fmaxf(v, red[256 + tid]);
        v = fmaxf(v, red[384 + tid]);
        v *= sFp[p0 + tid];  // apply A-row scale (positive, commutes with max)
        float d2 = fmaxf(2.0f - 2.0f * v, 0.0f);
        g_spatch[(size_t)pair * P + p0 + tid] = 0.5f * sqrtf(d2);
    }
}

// ---------------------------------------------------------------------------
// Kernel 3: scores[n] = mean_m max_p spatch; sp[n][p] = mean_m spatch.
// ---------------------------------------------------------------------------
__global__ void reduce_k(float* __restrict__ scores) {
    const int n = blockIdx.x;
    const int p = threadIdx.x;
    float v[8];
    float s = 0.f;
    #pragma unroll
    for (int m = 0; m < 8; m++) {
        v[m] = g_spatch[(size_t)(n * 8 + m) * P + p];
        s += v[m];
    }
    g_sp[n * P + p] = s * 0.125f;

    __shared__ int smax[8];
    if (p < 8) smax[p] = 0;  // dist >= 0 so int-compare == float-compare
    __syncthreads();
    #pragma unroll
    for (int m = 0; m < 8; m++) {
        float x = v[m];
        #pragma unroll
        for (int off = 16; off; off >>= 1)
            x = fmaxf(x, __shfl_xor_sync(0xffffffffu, x, off));
        if ((p & 31) == 0) atomicMax(&smax[m], __float_as_int(x));
    }
    __syncthreads();
    if (p == 0) {
        float t = 0.f;
        #pragma unroll
        for (int m = 0; m < 8; m++) t += __int_as_float(smax[m]);
        scores[n] = t * 0.125f;
    }
}

// ---------------------------------------------------------------------------
// Kernel 4: bilinear resize (8,32,32) -> (8,512,512)
// ---------------------------------------------------------------------------
__global__ void resize_k(float* __restrict__ out) {
    int idx = blockIdx.x * blockDim.x + threadIdx.x;
    if (idx >= N1 * OH * OW) return;
    int c = idx & (OW - 1);
    int r = (idx >> 9) & (OH - 1);
    int n = idx >> 18;
    float sy = (r + 0.5f) * ((float)PH / OH) - 0.5f;
    float sx = (c + 0.5f) * ((float)PW / OW) - 0.5f;
    float y0f = floorf(sy), x0f = floorf(sx);
    float wy = sy - y0f, wx = sx - x0f;
    int y0 = min(max((int)y0f, 0), PH - 1);
    int y1 = min(max((int)y0f + 1, 0), PH - 1);
    int x0 = min(max((int)x0f, 0), PW - 1);
    int x1 = min(max((int)x0f + 1, 0), PW - 1);
    const float* __restrict__ b = g_sp + n * (PH * PW);
    float v00 = b[y0 * PW + x0], v01 = b[y0 * PW + x1];
    float v10 = b[y1 * PW + x0], v11 = b[y1 * PW + x1];
    float top = v00 * (1.f - wx) + v01 * wx;
    float bot = v10 * (1.f - wx) + v11 * wx;
    out[idx] = top * (1.f - wy) + bot * wy;
}

// ---------------------------------------------------------------------------
extern "C" void kernel_launch(void* const* d_in, const int* in_sizes, int n_in,
                              void* d_out, int out_size) {
    (void)in_sizes; (void)n_in; (void)out_size;
    const float* feats  = (const float*)d_in[0];
    const float* nfeats = (const float*)d_in[1];
    float* out = (float*)d_out;  // [0..7] = scores, [8..] = scores_pixel

    cudaFuncSetAttribute(gemm_max_k,
                         cudaFuncAttributeMaxDynamicSharedMemorySize, SMEM_DYN);

    norm_k<<<(N1 + N2) * P, 192>>>(feats, nfeats);
    dim3 ggrid(P / BM, N1 * N2);
    gemm_max_k<<<ggrid, 256, SMEM_DYN>>>();
    reduce_k<<<N1, P>>>(out);
    resize_k<<<(N1 * OH * OW + 255) / 256, 256>>>(out + N1);
}

// round 11
// speedup vs baseline: 2.3159x; 1.1059x over previous
#include <cuda_runtime.h>
#include <cuda_bf16.h>
#include <math.h>
#include <stdint.h>

// Problem constants
#define N1 8
#define N2 8
#define P  1024
#define D  768
#define PH 32
#define PW 32
#define OH 512
#define OW 512

// GEMM tiling — INT8 IMMA path (mma.sync m16n8k32.s8), q-split units.
#define BM 128
#define BN 128
#define BK 64                     // 64 int8 = 64B per tile row
#define STAGES 3
#define KSTEPS (D / BK)           // 12
#define QSTEPS_U 4                // q-tiles per unit (half of 8)
#define NSTEP  (KSTEPS * QSTEPS_U)  // 48
#define TILE_BYTES  8192          // 128 rows * 64 B
#define STAGE_BYTES (2 * TILE_BYTES)
#define SMEM_TILES  (STAGES * STAGE_BYTES)   // 49152
#define SMEM_SBV    SMEM_TILES               // 128 floats of B scales
#define SMEM_DYN    (SMEM_TILES + 512)

// Scratch (no cudaMalloc allowed)
__device__ int8_t g_Fq[N1 * P * D];   // normalized feats, int8 (per-row scaled)
__device__ int8_t g_Gq[N2 * P * D];   // normalized nfeats, int8
__device__ float  g_sF[N1 * P];       // per-row scales for F
__device__ float  g_sG[N2 * P];       // per-row scales for G
__device__ float  g_spatch[N1 * N2 * P];  // biased max cos: cmax*sF + 2 (atomic)
__device__ float  g_sp[N1 * P];

// ---------------------------------------------------------------------------
// Helpers
// ---------------------------------------------------------------------------
__device__ __forceinline__ uint32_t cvta_s(const void* p) {
    return (uint32_t)__cvta_generic_to_shared(p);
}

#define CPA16(dst, src) \
    asm volatile("cp.async.cg.shared.global [%0], [%1], 16;\n" :: "r"(dst), "l"(src))
#define CPA_COMMIT()  asm volatile("cp.async.commit_group;\n" ::: "memory")
#define CPA_WAIT1()   asm volatile("cp.async.wait_group 1;\n" ::: "memory")

__device__ __forceinline__ void ldsm4(uint32_t& r0, uint32_t& r1, uint32_t& r2,
                                      uint32_t& r3, uint32_t a) {
    asm volatile("ldmatrix.sync.aligned.m8n8.x4.shared.b16 {%0,%1,%2,%3}, [%4];\n"
                 : "=r"(r0), "=r"(r1), "=r"(r2), "=r"(r3) : "r"(a));
}

__device__ __forceinline__ void mma16832s8(int* c, const uint32_t* a,
                                           const uint32_t* b) {
    asm volatile(
        "mma.sync.aligned.m16n8k32.row.col.s32.s8.s8.s32 "
        "{%0,%1,%2,%3}, {%4,%5,%6,%7}, {%8,%9}, {%0,%1,%2,%3};\n"
        : "+r"(c[0]), "+r"(c[1]), "+r"(c[2]), "+r"(c[3])
        : "r"(a[0]), "r"(a[1]), "r"(a[2]), "r"(a[3]), "r"(b[0]), "r"(b[1]));
}

// Tile row = 64 int8 = 64B = 4 chunks of 16B. XOR swizzle: conflict-free
// ldmatrix (8 rows at fixed logical chunk hit 8 distinct 16B slots mod 128B).
__device__ __forceinline__ uint32_t swaddr(int row, int ch) {
    return (uint32_t)((row << 6) | (((ch ^ ((row >> 1) & 3)) & 3) << 4));
}

// ---------------------------------------------------------------------------
// Kernel 1: row-normalize -> per-row-scaled int8; also zero-init g_spatch.
// grid = 16384 rows, block 192
// ---------------------------------------------------------------------------
__global__ void norm_k(const float* __restrict__ feats,
                       const float* __restrict__ nfeats) {
    int row = blockIdx.x;

    // init g_spatch (keys are >= 0.95, so 0.0f is the identity for float-max)
    if (row < N1 * N2) {
        for (int i = threadIdx.x; i < P; i += blockDim.x)
            g_spatch[(size_t)row * P + i] = 0.0f;
    }

    const float* src;
    int8_t* dst;
    float* sdst;
    int srow;
    if (row < N1 * P) {
        src = feats + (size_t)row * D;
        dst = g_Fq + (size_t)row * D;
        sdst = g_sF; srow = row;
    } else {
        int r = row - N1 * P;
        src = nfeats + (size_t)r * D;
        dst = g_Gq + (size_t)r * D;
        sdst = g_sG; srow = r;
    }
    int t = threadIdx.x;  // 0..191
    float4 x = *(const float4*)(src + t * 4);
    float s = x.x * x.x + x.y * x.y + x.z * x.z + x.w * x.w;
    #pragma unroll
    for (int off = 16; off; off >>= 1)
        s += __shfl_xor_sync(0xffffffffu, s, off);
    __shared__ float ws[6];
    __shared__ float rnorm_s, amax_s;
    if ((t & 31) == 0) ws[t >> 5] = s;
    __syncthreads();
    if (t == 0) {
        float tot = 0.f;
        #pragma unroll
        for (int i = 0; i < 6; i++) tot += ws[i];
        rnorm_s = 1.0f / sqrtf(tot);
    }
    __syncthreads();
    float r = rnorm_s;
    float y0 = x.x * r, y1 = x.y * r, y2 = x.z * r, y3 = x.w * r;

    float am = fmaxf(fmaxf(fabsf(y0), fabsf(y1)), fmaxf(fabsf(y2), fabsf(y3)));
    #pragma unroll
    for (int off = 16; off; off >>= 1)
        am = fmaxf(am, __shfl_xor_sync(0xffffffffu, am, off));
    if ((t & 31) == 0) ws[t >> 5] = am;
    __syncthreads();
    if (t == 0) {
        float mx = 0.f;
        #pragma unroll
        for (int i = 0; i < 6; i++) mx = fmaxf(mx, ws[i]);
        amax_s = mx;
        sdst[srow] = mx * (1.0f / 127.0f);
    }
    __syncthreads();
    float scale = 127.0f / amax_s;
    int q0 = __float2int_rn(y0 * scale);
    int q1 = __float2int_rn(y1 * scale);
    int q2 = __float2int_rn(y2 * scale);
    int q3 = __float2int_rn(y3 * scale);
    uint32_t pk = (uint32_t)(q0 & 0xff) | ((uint32_t)(q1 & 0xff) << 8) |
                  ((uint32_t)(q2 & 0xff) << 16) | ((uint32_t)(q3 & 0xff) << 24);
    *(uint32_t*)(dst + t * 4) = pk;
}

// ---------------------------------------------------------------------------
// Kernel 2: int8 tensor-core batched GEMM + running (scaled) max over q.
// grid = (8 p-blocks, 128 = pair*2 + qhalf): 1024 units of 48 steps ->
// wave-quantization tail ~1% (vs 15% at 512 units). Per-unit result merged
// into g_spatch via atomicMax on positive float keys (cmax*sF + 2).
// 256 threads = 8 warps (2 m-rows x 4 n-cols), warp tile 64m x 32n,
// mma.m16n8k32.s8, BK=64, 3-stage cp.async pipeline.
// ---------------------------------------------------------------------------
__global__ __launch_bounds__(256, 2)
void gemm_max_k() {
    extern __shared__ __align__(1024) unsigned char smem[];
    const uint32_t sbase = cvta_s(smem);
    float* sbv = (float*)(smem + SMEM_SBV);  // B scales for current q-pass

    const int pair = blockIdx.y >> 1;
    const int qh   = blockIdx.y & 1;         // q-half: 0 -> q 0..511, 1 -> 512..1023
    const int qbase = qh * (QSTEPS_U * BN);  // 0 or 512
    const int8_t* __restrict__ Fb = g_Fq + (size_t)(pair >> 3) * P * D;
    const int8_t* __restrict__ Gb = g_Gq + (size_t)(pair & 7) * P * D;
    const float* __restrict__ sFp = g_sF + (size_t)(pair >> 3) * P;
    const float* __restrict__ sGp = g_sG + (size_t)(pair & 7) * P;
    const int p0 = blockIdx.x * BM;

    const int tid  = threadIdx.x;
    const int lane = tid & 31;
    const int wid  = tid >> 5;
    const int wrow = (wid >> 2) * 64;  // warp m offset (0 / 64)
    const int wcol = (wid & 3) * 32;   // warp n offset (0..96)

    // loader mapping: thread -> (row = tid>>2 [+64], chunk = tid&3)
    const int lrow   = tid >> 2;  // 0..63
    const int lchunk = tid & 3;
    const uint32_t dA0 = swaddr(lrow, lchunk);
    const uint32_t dA1 = swaddr(lrow + 64, lchunk);

    int acc[4][4][4];
    float cmax[4][2];
    #pragma unroll
    for (int i = 0; i < 4; i++) { cmax[i][0] = -1e30f; cmax[i][1] = -1e30f; }
    #pragma unroll
    for (int i = 0; i < 4; i++)
        #pragma unroll
        for (int j = 0; j < 4; j++)
            #pragma unroll
            for (int e = 0; e < 4; e++) acc[i][j][e] = 0;

    // -------- cp.async tile loader for flattened step s --------
    auto load_step = [&](int s) {
        int q0 = qbase + (s / KSTEPS) * BN;
        int k0 = (s % KSTEPS) * BK;
        uint32_t Ab = sbase + (s % STAGES) * STAGE_BYTES;
        uint32_t Bb = Ab + TILE_BYTES;
        int ke = k0 + lchunk * 16;  // int8 elements
        CPA16(Ab + dA0, Fb + ((size_t)(p0 + lrow) * D + ke));
        CPA16(Ab + dA1, Fb + ((size_t)(p0 + lrow + 64) * D + ke));
        CPA16(Bb + dA0, Gb + ((size_t)(q0 + lrow) * D + ke));
        CPA16(Bb + dA1, Gb + ((size_t)(q0 + lrow + 64) * D + ke));
    };

    // prologue
    #pragma unroll
    for (int s = 0; s < STAGES - 1; s++) {
        load_step(s);
        CPA_COMMIT();
    }

    // per-warp ldmatrix lane offsets
    const int mr = lane & 15;        // row-within-16 for ldsm
    const int cl = lane >> 4;        // 16B chunk select (0/1)
    const int qb = wcol + 2 * (lane & 3);  // this lane's base q col in tile

    int kc = 0;  // position within current q-pass
    for (int s = 0; s < NSTEP; s++) {
        CPA_WAIT1();
        __syncthreads();

        // q-pass start: stage B scales for the fold (ordered by later syncs)
        if (kc == 0 && tid < 128)
            sbv[tid] = sGp[qbase + (s / KSTEPS) * BN + tid];

        uint32_t Ab = sbase + (s % STAGES) * STAGE_BYTES;
        uint32_t Bb = Ab + TILE_BYTES;

        #pragma unroll
        for (int hk = 0; hk < 2; hk++) {  // two k32 groups in BK=64
            uint32_t a[4][4], b[4][2];
            #pragma unroll
            for (int i = 0; i < 4; i++)
                ldsm4(a[i][0], a[i][1], a[i][2], a[i][3],
                      Ab + swaddr(wrow + i * 16 + mr, hk * 2 + cl));
            #pragma unroll
            for (int j = 0; j < 2; j++) {
                uint32_t r0, r1, r2, r3;
                ldsm4(r0, r1, r2, r3,
                      Bb + swaddr(wcol + j * 16 + mr, hk * 2 + cl));
                b[2 * j][0] = r0;     b[2 * j][1] = r2;
                b[2 * j + 1][0] = r1; b[2 * j + 1][1] = r3;
            }
            #pragma unroll
            for (int i = 0; i < 4; i++)
                #pragma unroll
                for (int j = 0; j < 4; j++)
                    mma16832s8(acc[i][j], a[i], b[j]);
        }

        // issue next stage (after MMA burst)
        if (s + STAGES - 1 < NSTEP) load_step(s + STAGES - 1);
        CPA_COMMIT();

        if (++kc == KSTEPS) {  // end of a q-pass: scale by sb[q], fold max
            kc = 0;
            #pragma unroll
            for (int i = 0; i < 4; i++) {
                float m0 = cmax[i][0], m1 = cmax[i][1];
                #pragma unroll
                for (int j = 0; j < 4; j++) {
                    float s0 = sbv[qb + j * 8];
                    float s1 = sbv[qb + j * 8 + 1];
                    m0 = fmaxf(m0, fmaxf((float)acc[i][j][0] * s0,
                                         (float)acc[i][j][1] * s1));
                    m1 = fmaxf(m1, fmaxf((float)acc[i][j][2] * s0,
                                         (float)acc[i][j][3] * s1));
                    acc[i][j][0] = 0; acc[i][j][1] = 0;
                    acc[i][j][2] = 0; acc[i][j][3] = 0;
                }
                cmax[i][0] = m0; cmax[i][1] = m1;
            }
        }
    }

    // reduce max over quad lanes (columns live in lane&3; sb already applied)
    #pragma unroll
    for (int i = 0; i < 4; i++) {
        #pragma unroll
        for (int e = 0; e < 2; e++) {
            float v = cmax[i][e];
            v = fmaxf(v, __shfl_xor_sync(0xffffffffu, v, 1));
            v = fmaxf(v, __shfl_xor_sync(0xffffffffu, v, 2));
            cmax[i][e] = v;
        }
    }

    __syncthreads();  // tiles dead; reuse smem for cross-warp max
    float* red = (float*)smem;  // [4 warp_cols][128 rows]
    if ((lane & 3) == 0) {
        int base = (wid & 3) * 128 + wrow;
        int r = lane >> 2;  // 0..7
        #pragma unroll
        for (int i = 0; i < 4; i++) {
            red[base + i * 16 + r]     = cmax[i][0];
            red[base + i * 16 + r + 8] = cmax[i][1];
        }
    }
    __syncthreads();
    if (tid < 128) {
        float v = red[tid];
        v = fmaxf(v, red[128 + tid]);
        v = fmaxf(v, red[256 + tid]);
        v = fmaxf(v, red[384 + tid]);
        v = v * sFp[p0 + tid] + 2.0f;  // key in [0.95, 3.05] > 0: int-max valid
        atomicMax((int*)&g_spatch[(size_t)pair * P + p0 + tid],
                  __float_as_int(v));
    }
}

// ---------------------------------------------------------------------------
// Kernel 3: decode keys -> dist, then scores[n] = mean_m max_p,
// sp[n][p] = mean_m. dist = 0.5*sqrt(max(2 - 2*(key-2), 0)).
// ---------------------------------------------------------------------------
__global__ void reduce_k(float* __restrict__ scores) {
    const int n = blockIdx.x;
    const int p = threadIdx.x;
    float v[8];
    float s = 0.f;
    #pragma unroll
    for (int m = 0; m < 8; m++) {
        float key = g_spatch[(size_t)(n * 8 + m) * P + p];
        float c = key - 2.0f;
        v[m] = 0.5f * sqrtf(fmaxf(2.0f - 2.0f * c, 0.0f));
        s += v[m];
    }
    g_sp[n * P + p] = s * 0.125f;

    __shared__ int smax[8];
    if (p < 8) smax[p] = 0;  // dist >= 0 so int-compare == float-compare
    __syncthreads();
    #pragma unroll
    for (int m = 0; m < 8; m++) {
        float x = v[m];
        #pragma unroll
        for (int off = 16; off; off >>= 1)
            x = fmaxf(x, __shfl_xor_sync(0xffffffffu, x, off));
        if ((p & 31) == 0) atomicMax(&smax[m], __float_as_int(x));
    }
    __syncthreads();
    if (p == 0) {
        float t = 0.f;
        #pragma unroll
        for (int m = 0; m < 8; m++) t += __int_as_float(smax[m]);
        scores[n] = t * 0.125f;
    }
}

// ---------------------------------------------------------------------------
// Kernel 4: bilinear resize (8,32,32) -> (8,512,512)
// ---------------------------------------------------------------------------
__global__ void resize_k(float* __restrict__ out) {
    int idx = blockIdx.x * blockDim.x + threadIdx.x;
    if (idx >= N1 * OH * OW) return;
    int c = idx & (OW - 1);
    int r = (idx >> 9) & (OH - 1);
    int n = idx >> 18;
    float sy = (r + 0.5f) * ((float)PH / OH) - 0.5f;
    float sx = (c + 0.5f) * ((float)PW / OW) - 0.5f;
    float y0f = floorf(sy), x0f = floorf(sx);
    float wy = sy - y0f, wx = sx - x0f;
    int y0 = min(max((int)y0f, 0), PH - 1);
    int y1 = min(max((int)y0f + 1, 0), PH - 1);
    int x0 = min(max((int)x0f, 0), PW - 1);
    int x1 = min(max((int)x0f + 1, 0), PW - 1);
    const float* __restrict__ b = g_sp + n * (PH * PW);
    float v00 = b[y0 * PW + x0], v01 = b[y0 * PW + x1];
    float v10 = b[y1 * PW + x0], v11 = b[y1 * PW + x1];
    float top = v00 * (1.f - wx) + v01 * wx;
    float bot = v10 * (1.f - wx) + v11 * wx;
    out[idx] = top * (1.f - wy) + bot * wy;
}

// ---------------------------------------------------------------------------
extern "C" void kernel_launch(void* const* d_in, const int* in_sizes, int n_in,
                              void* d_out, int out_size) {
    (void)in_sizes; (void)n_in; (void)out_size;
    const float* feats  = (const float*)d_in[0];
    const float* nfeats = (const float*)d_in[1];
    float* out = (float*)d_out;  // [0..7] = scores, [8..] = scores_pixel

    cudaFuncSetAttribute(gemm_max_k,
                         cudaFuncAttributeMaxDynamicSharedMemorySize, SMEM_DYN);

    norm_k<<<(N1 + N2) * P, 192>>>(feats, nfeats);
    dim3 ggrid(P / BM, N1 * N2 * 2);  // 1024 units: (pblock, pair*2 + qhalf)
    gemm_max_k<<<ggrid, 256, SMEM_DYN>>>();
    reduce_k<<<N1, P>>>(out);
    resize_k<<<(N1 * OH * OW + 255) / 256, 256>>>(out + N1);
}

// round 12
// speedup vs baseline: 2.3748x; 1.0255x over previous
#include <cuda_runtime.h>
#include <cuda_bf16.h>
#include <math.h>
#include <stdint.h>

// Problem constants
#define N1 8
#define N2 8
#define P  1024
#define D  768
#define PH 32
#define PW 32
#define OH 512
#define OW 512

// GEMM tiling — INT8 IMMA path (mma.sync m16n8k32.s8), q-split units.
#define BM 128
#define BN 128
#define BK 64                     // 64 int8 = 64B per tile row
#define STAGES 3
#define KSTEPS (D / BK)           // 12
#define QSTEPS_U 4                // q-tiles per unit (half of 8)
#define NSTEP  (KSTEPS * QSTEPS_U)  // 48
#define TILE_BYTES  8192          // 128 rows * 64 B
#define STAGE_BYTES (2 * TILE_BYTES)
#define SMEM_TILES  (STAGES * STAGE_BYTES)   // 49152
#define SMEM_SBV    SMEM_TILES               // 128 floats of B scales
#define SMEM_DYN    (SMEM_TILES + 512)

// Scratch (no cudaMalloc allowed)
__device__ int8_t g_Fq[N1 * P * D];   // normalized feats, int8 (per-row scaled)
__device__ int8_t g_Gq[N2 * P * D];   // normalized nfeats, int8
__device__ float  g_sF[N1 * P];       // per-row scales for F
__device__ float  g_sG[N2 * P];       // per-row scales for G
__device__ float  g_spatch[N1 * N2 * P];  // biased max cos: cmax*sF + 2 (atomic)
__device__ float  g_sp[N1 * P];

// ---------------------------------------------------------------------------
// Helpers
// ---------------------------------------------------------------------------
__device__ __forceinline__ uint32_t cvta_s(const void* p) {
    return (uint32_t)__cvta_generic_to_shared(p);
}

#define CPA16(dst, src) \
    asm volatile("cp.async.cg.shared.global [%0], [%1], 16;\n" :: "r"(dst), "l"(src))
#define CPA_COMMIT()  asm volatile("cp.async.commit_group;\n" ::: "memory")
#define CPA_WAIT1()   asm volatile("cp.async.wait_group 1;\n" ::: "memory")

__device__ __forceinline__ void ldsm4(uint32_t& r0, uint32_t& r1, uint32_t& r2,
                                      uint32_t& r3, uint32_t a) {
    asm volatile("ldmatrix.sync.aligned.m8n8.x4.shared.b16 {%0,%1,%2,%3}, [%4];\n"
                 : "=r"(r0), "=r"(r1), "=r"(r2), "=r"(r3) : "r"(a));
}

__device__ __forceinline__ void mma16832s8(int* c, const uint32_t* a,
                                           const uint32_t* b) {
    asm volatile(
        "mma.sync.aligned.m16n8k32.row.col.s32.s8.s8.s32 "
        "{%0,%1,%2,%3}, {%4,%5,%6,%7}, {%8,%9}, {%0,%1,%2,%3};\n"
        : "+r"(c[0]), "+r"(c[1]), "+r"(c[2]), "+r"(c[3])
        : "r"(a[0]), "r"(a[1]), "r"(a[2]), "r"(a[3]), "r"(b[0]), "r"(b[1]));
}

// Tile row = 64 int8 = 64B = 4 chunks of 16B. XOR swizzle: conflict-free
// ldmatrix (8 rows at fixed logical chunk hit 8 distinct 16B slots mod 128B).
__device__ __forceinline__ uint32_t swaddr(int row, int ch) {
    return (uint32_t)((row << 6) | (((ch ^ ((row >> 1) & 3)) & 3) << 4));
}

// ---------------------------------------------------------------------------
// Kernel 1: row-normalize -> per-row-scaled int8; also zero-init g_spatch.
// Single fused reduction round: q = round(x*127/amax(x)) needs no rnorm;
// the stored dequant scale is amax(x)*rnorm/127.
// grid = 16384 rows, block 192
// ---------------------------------------------------------------------------
__global__ void norm_k(const float* __restrict__ feats,
                       const float* __restrict__ nfeats) {
    int row = blockIdx.x;

    // init g_spatch (keys are >= 0.95, so 0.0f is the identity for float-max)
    if (row < N1 * N2) {
        for (int i = threadIdx.x; i < P; i += blockDim.x)
            g_spatch[(size_t)row * P + i] = 0.0f;
    }

    const float* src;
    int8_t* dst;
    float* sdst;
    int srow;
    if (row < N1 * P) {
        src = feats + (size_t)row * D;
        dst = g_Fq + (size_t)row * D;
        sdst = g_sF; srow = row;
    } else {
        int r = row - N1 * P;
        src = nfeats + (size_t)r * D;
        dst = g_Gq + (size_t)r * D;
        sdst = g_sG; srow = r;
    }
    int t = threadIdx.x;  // 0..191
    float4 x = *(const float4*)(src + t * 4);
    float s = x.x * x.x + x.y * x.y + x.z * x.z + x.w * x.w;
    float am = fmaxf(fmaxf(fabsf(x.x), fabsf(x.y)),
                     fmaxf(fabsf(x.z), fabsf(x.w)));
    #pragma unroll
    for (int off = 16; off; off >>= 1) {
        s  += __shfl_xor_sync(0xffffffffu, s, off);
        am  = fmaxf(am, __shfl_xor_sync(0xffffffffu, am, off));
    }
    __shared__ float ws[6], wm[6];
    __shared__ float scale_s, sc_out;
    if ((t & 31) == 0) { ws[t >> 5] = s; wm[t >> 5] = am; }
    __syncthreads();
    if (t == 0) {
        float tot = 0.f, mx = 0.f;
        #pragma unroll
        for (int i = 0; i < 6; i++) { tot += ws[i]; mx = fmaxf(mx, wm[i]); }
        float rnorm = rsqrtf(tot);
        scale_s = 127.0f / mx;                  // raw-x quantizer
        sc_out  = mx * rnorm * (1.0f / 127.0f); // dequant scale (unit-norm space)
    }
    __syncthreads();
    if (t == 0) sdst[srow] = sc_out;
    float scale = scale_s;
    int q0 = __float2int_rn(x.x * scale);
    int q1 = __float2int_rn(x.y * scale);
    int q2 = __float2int_rn(x.z * scale);
    int q3 = __float2int_rn(x.w * scale);
    uint32_t pk = (uint32_t)(q0 & 0xff) | ((uint32_t)(q1 & 0xff) << 8) |
                  ((uint32_t)(q2 & 0xff) << 16) | ((uint32_t)(q3 & 0xff) << 24);
    *(uint32_t*)(dst + t * 4) = pk;
}

// ---------------------------------------------------------------------------
// Kernel 2: int8 tensor-core batched GEMM + running (scaled) max over q.
// grid = (8 p-blocks, 128 = pair*2 + qhalf): 1024 units of 48 steps.
// Byte-identical to the R11 gemm (at ~97% of IMMA issue ceiling).
// ---------------------------------------------------------------------------
__global__ __launch_bounds__(256, 2)
void gemm_max_k() {
    extern __shared__ __align__(1024) unsigned char smem[];
    const uint32_t sbase = cvta_s(smem);
    float* sbv = (float*)(smem + SMEM_SBV);  // B scales for current q-pass

    const int pair = blockIdx.y >> 1;
    const int qh   = blockIdx.y & 1;         // q-half: 0 -> q 0..511, 1 -> 512..1023
    const int qbase = qh * (QSTEPS_U * BN);  // 0 or 512
    const int8_t* __restrict__ Fb = g_Fq + (size_t)(pair >> 3) * P * D;
    const int8_t* __restrict__ Gb = g_Gq + (size_t)(pair & 7) * P * D;
    const float* __restrict__ sFp = g_sF + (size_t)(pair >> 3) * P;
    const float* __restrict__ sGp = g_sG + (size_t)(pair & 7) * P;
    const int p0 = blockIdx.x * BM;

    const int tid  = threadIdx.x;
    const int lane = tid & 31;
    const int wid  = tid >> 5;
    const int wrow = (wid >> 2) * 64;  // warp m offset (0 / 64)
    const int wcol = (wid & 3) * 32;   // warp n offset (0..96)

    // loader mapping: thread -> (row = tid>>2 [+64], chunk = tid&3)
    const int lrow   = tid >> 2;  // 0..63
    const int lchunk = tid & 3;
    const uint32_t dA0 = swaddr(lrow, lchunk);
    const uint32_t dA1 = swaddr(lrow + 64, lchunk);

    int acc[4][4][4];
    float cmax[4][2];
    #pragma unroll
    for (int i = 0; i < 4; i++) { cmax[i][0] = -1e30f; cmax[i][1] = -1e30f; }
    #pragma unroll
    for (int i = 0; i < 4; i++)
        #pragma unroll
        for (int j = 0; j < 4; j++)
            #pragma unroll
            for (int e = 0; e < 4; e++) acc[i][j][e] = 0;

    // -------- cp.async tile loader for flattened step s --------
    auto load_step = [&](int s) {
        int q0 = qbase + (s / KSTEPS) * BN;
        int k0 = (s % KSTEPS) * BK;
        uint32_t Ab = sbase + (s % STAGES) * STAGE_BYTES;
        uint32_t Bb = Ab + TILE_BYTES;
        int ke = k0 + lchunk * 16;  // int8 elements
        CPA16(Ab + dA0, Fb + ((size_t)(p0 + lrow) * D + ke));
        CPA16(Ab + dA1, Fb + ((size_t)(p0 + lrow + 64) * D + ke));
        CPA16(Bb + dA0, Gb + ((size_t)(q0 + lrow) * D + ke));
        CPA16(Bb + dA1, Gb + ((size_t)(q0 + lrow + 64) * D + ke));
    };

    // prologue
    #pragma unroll
    for (int s = 0; s < STAGES - 1; s++) {
        load_step(s);
        CPA_COMMIT();
    }

    // per-warp ldmatrix lane offsets
    const int mr = lane & 15;        // row-within-16 for ldsm
    const int cl = lane >> 4;        // 16B chunk select (0/1)
    const int qb = wcol + 2 * (lane & 3);  // this lane's base q col in tile

    int kc = 0;  // position within current q-pass
    for (int s = 0; s < NSTEP; s++) {
        CPA_WAIT1();
        __syncthreads();

        // q-pass start: stage B scales for the fold (ordered by later syncs)
        if (kc == 0 && tid < 128)
            sbv[tid] = sGp[qbase + (s / KSTEPS) * BN + tid];

        uint32_t Ab = sbase + (s % STAGES) * STAGE_BYTES;
        uint32_t Bb = Ab + TILE_BYTES;

        #pragma unroll
        for (int hk = 0; hk < 2; hk++) {  // two k32 groups in BK=64
            uint32_t a[4][4], b[4][2];
            #pragma unroll
            for (int i = 0; i < 4; i++)
                ldsm4(a[i][0], a[i][1], a[i][2], a[i][3],
                      Ab + swaddr(wrow + i * 16 + mr, hk * 2 + cl));
            #pragma unroll
            for (int j = 0; j < 2; j++) {
                uint32_t r0, r1, r2, r3;
                ldsm4(r0, r1, r2, r3,
                      Bb + swaddr(wcol + j * 16 + mr, hk * 2 + cl));
                b[2 * j][0] = r0;     b[2 * j][1] = r2;
                b[2 * j + 1][0] = r1; b[2 * j + 1][1] = r3;
            }
            #pragma unroll
            for (int i = 0; i < 4; i++)
                #pragma unroll
                for (int j = 0; j < 4; j++)
                    mma16832s8(acc[i][j], a[i], b[j]);
        }

        // issue next stage (after MMA burst)
        if (s + STAGES - 1 < NSTEP) load_step(s + STAGES - 1);
        CPA_COMMIT();

        if (++kc == KSTEPS) {  // end of a q-pass: scale by sb[q], fold max
            kc = 0;
            #pragma unroll
            for (int i = 0; i < 4; i++) {
                float m0 = cmax[i][0], m1 = cmax[i][1];
                #pragma unroll
                for (int j = 0; j < 4; j++) {
                    float s0 = sbv[qb + j * 8];
                    float s1 = sbv[qb + j * 8 + 1];
                    m0 = fmaxf(m0, fmaxf((float)acc[i][j][0] * s0,
                                         (float)acc[i][j][1] * s1));
                    m1 = fmaxf(m1, fmaxf((float)acc[i][j][2] * s0,
                                         (float)acc[i][j][3] * s1));
                    acc[i][j][0] = 0; acc[i][j][1] = 0;
                    acc[i][j][2] = 0; acc[i][j][3] = 0;
                }
                cmax[i][0] = m0; cmax[i][1] = m1;
            }
        }
    }

    // reduce max over quad lanes (columns live in lane&3; sb already applied)
    #pragma unroll
    for (int i = 0; i < 4; i++) {
        #pragma unroll
        for (int e = 0; e < 2; e++) {
            float v = cmax[i][e];
            v = fmaxf(v, __shfl_xor_sync(0xffffffffu, v, 1));
            v = fmaxf(v, __shfl_xor_sync(0xffffffffu, v, 2));
            cmax[i][e] = v;
        }
    }

    __syncthreads();  // tiles dead; reuse smem for cross-warp max
    float* red = (float*)smem;  // [4 warp_cols][128 rows]
    if ((lane & 3) == 0) {
        int base = (wid & 3) * 128 + wrow;
        int r = lane >> 2;  // 0..7
        #pragma unroll
        for (int i = 0; i < 4; i++) {
            red[base + i * 16 + r]     = cmax[i][0];
            red[base + i * 16 + r + 8] = cmax[i][1];
        }
    }
    __syncthreads();
    if (tid < 128) {
        float v = red[tid];
        v = fmaxf(v, red[128 + tid]);
        v = fmaxf(v, red[256 + tid]);
        v = fmaxf(v, red[384 + tid]);
        v = v * sFp[p0 + tid] + 2.0f;  // key in [0.95, 3.05] > 0: int-max valid
        atomicMax((int*)&g_spatch[(size_t)pair * P + p0 + tid],
                  __float_as_int(v));
    }
}

// ---------------------------------------------------------------------------
// Kernel 3: decode keys -> dist, then scores[n] = mean_m max_p,
// sp[n][p] = mean_m. dist = 0.5*sqrt(max(2 - 2*(key-2), 0)).
// ---------------------------------------------------------------------------
__global__ void reduce_k(float* __restrict__ scores) {
    const int n = blockIdx.x;
    const int p = threadIdx.x;
    float v[8];
    float s = 0.f;
    #pragma unroll
    for (int m = 0; m < 8; m++) {
        float key = g_spatch[(size_t)(n * 8 + m) * P + p];
        float c = key - 2.0f;
        v[m] = 0.5f * sqrtf(fmaxf(2.0f - 2.0f * c, 0.0f));
        s += v[m];
    }
    g_sp[n * P + p] = s * 0.125f;

    __shared__ int smax[8];
    if (p < 8) smax[p] = 0;  // dist >= 0 so int-compare == float-compare
    __syncthreads();
    #pragma unroll
    for (int m = 0; m < 8; m++) {
        float x = v[m];
        #pragma unroll
        for (int off = 16; off; off >>= 1)
            x = fmaxf(x, __shfl_xor_sync(0xffffffffu, x, off));
        if ((p & 31) == 0) atomicMax(&smax[m], __float_as_int(x));
    }
    __syncthreads();
    if (p == 0) {
        float t = 0.f;
        #pragma unroll
        for (int m = 0; m < 8; m++) t += __int_as_float(smax[m]);
        scores[n] = t * 0.125f;
    }
}

// ---------------------------------------------------------------------------
// Kernel 4: bilinear resize (8,32,32) -> (8,512,512).
// One block per output row; source rows staged in smem; each thread writes
// one float4 (4 pixels). grid = 8*512, block = 128.
// ---------------------------------------------------------------------------
__global__ void resize_k(float* __restrict__ out) {
    const int n = blockIdx.x >> 9;         // image
    const int r = blockIdx.x & (OH - 1);   // output row
    const int t = threadIdx.x;             // 0..127, pixels 4t..4t+3

    __shared__ float r0s[PW], r1s[PW];
    {
        float sy = (r + 0.5f) * ((float)PH / OH) - 0.5f;
        float y0f = floorf(sy);
        int y0 = min(max((int)y0f, 0), PH - 1);
        int y1 = min(max((int)y0f + 1, 0), PH - 1);
        const float* __restrict__ b = g_sp + n * (PH * PW);
        if (t < PW)            r0s[t] = b[y0 * PW + t];
        else if (t < 2 * PW)   r1s[t - PW] = b[y1 * PW + (t - PW)];
    }
    __syncthreads();

    float sy = (r + 0.5f) * ((float)PH / OH) - 0.5f;
    float wy = sy - floorf(sy);
    float4 o;
    float* op = &o.x;
    #pragma unroll
    for (int k = 0; k < 4; k++) {
        int c = 4 * t + k;
        float sx = (c + 0.5f) * ((float)PW / OW) - 0.5f;
        float x0f = floorf(sx);
        float wx = sx - x0f;
        int x0 = min(max((int)x0f, 0), PW - 1);
        int x1 = min(max((int)x0f + 1, 0), PW - 1);
        float top = r0s[x0] + (r0s[x1] - r0s[x0]) * wx;
        float bot = r1s[x0] + (r1s[x1] - r1s[x0]) * wx;
        op[k] = top + (bot - top) * wy;
    }
    *(float4*)(out + ((size_t)n * OH + r) * OW + 4 * t) = o;
}

// ---------------------------------------------------------------------------
extern "C" void kernel_launch(void* const* d_in, const int* in_sizes, int n_in,
                              void* d_out, int out_size) {
    (void)in_sizes; (void)n_in; (void)out_size;
    const float* feats  = (const float*)d_in[0];
    const float* nfeats = (const float*)d_in[1];
    float* out = (float*)d_out;  // [0..7] = scores, [8..] = scores_pixel

    cudaFuncSetAttribute(gemm_max_k,
                         cudaFuncAttributeMaxDynamicSharedMemorySize, SMEM_DYN);

    norm_k<<<(N1 + N2) * P, 192>>>(feats, nfeats);
    dim3 ggrid(P / BM, N1 * N2 * 2);  // 1024 units: (pblock, pair*2 + qhalf)
    gemm_max_k<<<ggrid, 256, SMEM_DYN>>>();
    reduce_k<<<N1, P>>>(out);
    resize_k<<<N1 * OH, 128>>>(out + N1);
}

// round 13
// speedup vs baseline: 2.3996x; 1.0104x over previous
#include <cuda_runtime.h>
#include <cuda_bf16.h>
#include <math.h>
#include <stdint.h>

// Problem constants
#define N1 8
#define N2 8
#define P  1024
#define D  768
#define PH 32
#define PW 32
#define OH 512
#define OW 512

// GEMM tiling — INT8 IMMA path (mma.sync m16n8k32.s8), q-split units.
#define BM 128
#define BN 128
#define BK 64                     // 64 int8 = 64B per tile row
#define STAGES 4                  // 4-deep ring: 2 groups of latency slack
#define KSTEPS (D / BK)           // 12
#define QSTEPS_U 4                // q-tiles per unit (half of 8)
#define NSTEP  (KSTEPS * QSTEPS_U)  // 48
#define TILE_BYTES  8192          // 128 rows * 64 B
#define STAGE_BYTES (2 * TILE_BYTES)
#define SMEM_TILES  (STAGES * STAGE_BYTES)   // 65536
#define SMEM_SBV    SMEM_TILES               // 128 floats of B scales
#define SMEM_DYN    (SMEM_TILES + 512)

// Scratch (no cudaMalloc allowed)
__device__ int8_t g_Fq[N1 * P * D];   // normalized feats, int8 (per-row scaled)
__device__ int8_t g_Gq[N2 * P * D];   // normalized nfeats, int8
__device__ float  g_sF[N1 * P];       // per-row scales for F
__device__ float  g_sG[N2 * P];       // per-row scales for G
__device__ float  g_spatch[N1 * N2 * P];  // biased max cos: cmax*sF + 2 (atomic)
__device__ float  g_sp[N1 * P];

// ---------------------------------------------------------------------------
// Helpers
// ---------------------------------------------------------------------------
__device__ __forceinline__ uint32_t cvta_s(const void* p) {
    return (uint32_t)__cvta_generic_to_shared(p);
}

#define CPA16(dst, src) \
    asm volatile("cp.async.cg.shared.global [%0], [%1], 16;\n" :: "r"(dst), "l"(src))
#define CPA_COMMIT()  asm volatile("cp.async.commit_group;\n" ::: "memory")
#define CPA_WAIT2()   asm volatile("cp.async.wait_group 2;\n" ::: "memory")

__device__ __forceinline__ void ldsm4(uint32_t& r0, uint32_t& r1, uint32_t& r2,
                                      uint32_t& r3, uint32_t a) {
    asm volatile("ldmatrix.sync.aligned.m8n8.x4.shared.b16 {%0,%1,%2,%3}, [%4];\n"
                 : "=r"(r0), "=r"(r1), "=r"(r2), "=r"(r3) : "r"(a));
}

__device__ __forceinline__ void mma16832s8(int* c, const uint32_t* a,
                                           const uint32_t* b) {
    asm volatile(
        "mma.sync.aligned.m16n8k32.row.col.s32.s8.s8.s32 "
        "{%0,%1,%2,%3}, {%4,%5,%6,%7}, {%8,%9}, {%0,%1,%2,%3};\n"
        : "+r"(c[0]), "+r"(c[1]), "+r"(c[2]), "+r"(c[3])
        : "r"(a[0]), "r"(a[1]), "r"(a[2]), "r"(a[3]), "r"(b[0]), "r"(b[1]));
}

// Tile row = 64 int8 = 64B = 4 chunks of 16B. XOR swizzle: conflict-free
// ldmatrix (8 rows at fixed logical chunk hit 8 distinct 16B slots mod 128B).
__device__ __forceinline__ uint32_t swaddr(int row, int ch) {
    return (uint32_t)((row << 6) | (((ch ^ ((row >> 1) & 3)) & 3) << 4));
}

// ---------------------------------------------------------------------------
// Kernel 1: row-normalize -> per-row-scaled int8; also zero-init g_spatch.
// Single fused reduction round: q = round(x*127/amax(x)) needs no rnorm;
// the stored dequant scale is amax(x)*rnorm/127. grid = 16384 rows, block 192
// ---------------------------------------------------------------------------
__global__ void norm_k(const float* __restrict__ feats,
                       const float* __restrict__ nfeats) {
    int row = blockIdx.x;

    // init g_spatch (keys are >= 0.95, so 0.0f is the identity for float-max)
    if (row < N1 * N2) {
        for (int i = threadIdx.x; i < P; i += blockDim.x)
            g_spatch[(size_t)row * P + i] = 0.0f;
    }

    const float* src;
    int8_t* dst;
    float* sdst;
    int srow;
    if (row < N1 * P) {
        src = feats + (size_t)row * D;
        dst = g_Fq + (size_t)row * D;
        sdst = g_sF; srow = row;
    } else {
        int r = row - N1 * P;
        src = nfeats + (size_t)r * D;
        dst = g_Gq + (size_t)r * D;
        sdst = g_sG; srow = r;
    }
    int t = threadIdx.x;  // 0..191
    float4 x = *(const float4*)(src + t * 4);
    float s = x.x * x.x + x.y * x.y + x.z * x.z + x.w * x.w;
    float am = fmaxf(fmaxf(fabsf(x.x), fabsf(x.y)),
                     fmaxf(fabsf(x.z), fabsf(x.w)));
    #pragma unroll
    for (int off = 16; off; off >>= 1) {
        s  += __shfl_xor_sync(0xffffffffu, s, off);
        am  = fmaxf(am, __shfl_xor_sync(0xffffffffu, am, off));
    }
    __shared__ float ws[6], wm[6];
    __shared__ float scale_s, sc_out;
    if ((t & 31) == 0) { ws[t >> 5] = s; wm[t >> 5] = am; }
    __syncthreads();
    if (t == 0) {
        float tot = 0.f, mx = 0.f;
        #pragma unroll
        for (int i = 0; i < 6; i++) { tot += ws[i]; mx = fmaxf(mx, wm[i]); }
        float rnorm = rsqrtf(tot);
        scale_s = 127.0f / mx;                  // raw-x quantizer
        sc_out  = mx * rnorm * (1.0f / 127.0f); // dequant scale (unit-norm space)
    }
    __syncthreads();
    if (t == 0) sdst[srow] = sc_out;
    float scale = scale_s;
    int q0 = __float2int_rn(x.x * scale);
    int q1 = __float2int_rn(x.y * scale);
    int q2 = __float2int_rn(x.z * scale);
    int q3 = __float2int_rn(x.w * scale);
    uint32_t pk = (uint32_t)(q0 & 0xff) | ((uint32_t)(q1 & 0xff) << 8) |
                  ((uint32_t)(q2 & 0xff) << 16) | ((uint32_t)(q3 & 0xff) << 24);
    *(uint32_t*)(dst + t * 4) = pk;
}

// ---------------------------------------------------------------------------
// Kernel 2: int8 tensor-core batched GEMM + running (scaled) max over q.
// grid = (8 p-blocks, 128 = pair*2 + qhalf): 1024 units of 48 steps.
// 4-stage cp.async ring (only change vs R12): wait_group 2 keeps two full
// groups of latency slack to absorb L2 hit-latency jitter.
// ---------------------------------------------------------------------------
__global__ __launch_bounds__(256, 2)
void gemm_max_k() {
    extern __shared__ __align__(1024) unsigned char smem[];
    const uint32_t sbase = cvta_s(smem);
    float* sbv = (float*)(smem + SMEM_SBV);  // B scales for current q-pass

    const int pair = blockIdx.y >> 1;
    const int qh   = blockIdx.y & 1;         // q-half: 0 -> q 0..511, 1 -> 512..1023
    const int qbase = qh * (QSTEPS_U * BN);  // 0 or 512
    const int8_t* __restrict__ Fb = g_Fq + (size_t)(pair >> 3) * P * D;
    const int8_t* __restrict__ Gb = g_Gq + (size_t)(pair & 7) * P * D;
    const float* __restrict__ sFp = g_sF + (size_t)(pair >> 3) * P;
    const float* __restrict__ sGp = g_sG + (size_t)(pair & 7) * P;
    const int p0 = blockIdx.x * BM;

    const int tid  = threadIdx.x;
    const int lane = tid & 31;
    const int wid  = tid >> 5;
    const int wrow = (wid >> 2) * 64;  // warp m offset (0 / 64)
    const int wcol = (wid & 3) * 32;   // warp n offset (0..96)

    // loader mapping: thread -> (row = tid>>2 [+64], chunk = tid&3)
    const int lrow   = tid >> 2;  // 0..63
    const int lchunk = tid & 3;
    const uint32_t dA0 = swaddr(lrow, lchunk);
    const uint32_t dA1 = swaddr(lrow + 64, lchunk);

    int acc[4][4][4];
    float cmax[4][2];
    #pragma unroll
    for (int i = 0; i < 4; i++) { cmax[i][0] = -1e30f; cmax[i][1] = -1e30f; }
    #pragma unroll
    for (int i = 0; i < 4; i++)
        #pragma unroll
        for (int j = 0; j < 4; j++)
            #pragma unroll
            for (int e = 0; e < 4; e++) acc[i][j][e] = 0;

    // -------- cp.async tile loader for flattened step s --------
    auto load_step = [&](int s) {
        int q0 = qbase + (s / KSTEPS) * BN;
        int k0 = (s % KSTEPS) * BK;
        uint32_t Ab = sbase + (s % STAGES) * STAGE_BYTES;
        uint32_t Bb = Ab + TILE_BYTES;
        int ke = k0 + lchunk * 16;  // int8 elements
        CPA16(Ab + dA0, Fb + ((size_t)(p0 + lrow) * D + ke));
        CPA16(Ab + dA1, Fb + ((size_t)(p0 + lrow + 64) * D + ke));
        CPA16(Bb + dA0, Gb + ((size_t)(q0 + lrow) * D + ke));
        CPA16(Bb + dA1, Gb + ((size_t)(q0 + lrow + 64) * D + ke));
    };

    // prologue: fill STAGES-1 = 3 stages
    #pragma unroll
    for (int s = 0; s < STAGES - 1; s++) {
        load_step(s);
        CPA_COMMIT();
    }

    // per-warp ldmatrix lane offsets
    const int mr = lane & 15;        // row-within-16 for ldsm
    const int cl = lane >> 4;        // 16B chunk select (0/1)
    const int qb = wcol + 2 * (lane & 3);  // this lane's base q col in tile

    int kc = 0;  // position within current q-pass
    for (int s = 0; s < NSTEP; s++) {
        CPA_WAIT2();   // step-s group done; groups s+1, s+2 may remain in flight
        __syncthreads();

        // q-pass start: stage B scales for the fold (ordered by later syncs)
        if (kc == 0 && tid < 128)
            sbv[tid] = sGp[qbase + (s / KSTEPS) * BN + tid];

        uint32_t Ab = sbase + (s % STAGES) * STAGE_BYTES;
        uint32_t Bb = Ab + TILE_BYTES;

        #pragma unroll
        for (int hk = 0; hk < 2; hk++) {  // two k32 groups in BK=64
            uint32_t a[4][4], b[4][2];
            #pragma unroll
            for (int i = 0; i < 4; i++)
                ldsm4(a[i][0], a[i][1], a[i][2], a[i][3],
                      Ab + swaddr(wrow + i * 16 + mr, hk * 2 + cl));
            #pragma unroll
            for (int j = 0; j < 2; j++) {
                uint32_t r0, r1, r2, r3;
                ldsm4(r0, r1, r2, r3,
                      Bb + swaddr(wcol + j * 16 + mr, hk * 2 + cl));
                b[2 * j][0] = r0;     b[2 * j][1] = r2;
                b[2 * j + 1][0] = r1; b[2 * j + 1][1] = r3;
            }
            #pragma unroll
            for (int i = 0; i < 4; i++)
                #pragma unroll
                for (int j = 0; j < 4; j++)
                    mma16832s8(acc[i][j], a[i], b[j]);
        }

        // issue next stage (stage (s+3)%4 was last read at step s-1)
        if (s + STAGES - 1 < NSTEP) load_step(s + STAGES - 1);
        CPA_COMMIT();

        if (++kc == KSTEPS) {  // end of a q-pass: scale by sb[q], fold max
            kc = 0;
            #pragma unroll
            for (int i = 0; i < 4; i++) {
                float m0 = cmax[i][0], m1 = cmax[i][1];
                #pragma unroll
                for (int j = 0; j < 4; j++) {
                    float s0 = sbv[qb + j * 8];
                    float s1 = sbv[qb + j * 8 + 1];
                    m0 = fmaxf(m0, fmaxf((float)acc[i][j][0] * s0,
                                         (float)acc[i][j][1] * s1));
                    m1 = fmaxf(m1, fmaxf((float)acc[i][j][2] * s0,
                                         (float)acc[i][j][3] * s1));
                    acc[i][j][0] = 0; acc[i][j][1] = 0;
                    acc[i][j][2] = 0; acc[i][j][3] = 0;
                }
                cmax[i][0] = m0; cmax[i][1] = m1;
            }
        }
    }

    // reduce max over quad lanes (columns live in lane&3; sb already applied)
    #pragma unroll
    for (int i = 0; i < 4; i++) {
        #pragma unroll
        for (int e = 0; e < 2; e++) {
            float v = cmax[i][e];
            v = fmaxf(v, __shfl_xor_sync(0xffffffffu, v, 1));
            v = fmaxf(v, __shfl_xor_sync(0xffffffffu, v, 2));
            cmax[i][e] = v;
        }
    }

    __syncthreads();  // tiles dead; reuse smem for cross-warp max
    float* red = (float*)smem;  // [4 warp_cols][128 rows]
    if ((lane & 3) == 0) {
        int base = (wid & 3) * 128 + wrow;
        int r = lane >> 2;  // 0..7
        #pragma unroll
        for (int i = 0; i < 4; i++) {
            red[base + i * 16 + r]     = cmax[i][0];
            red[base + i * 16 + r + 8] = cmax[i][1];
        }
    }
    __syncthreads();
    if (tid < 128) {
        float v = red[tid];
        v = fmaxf(v, red[128 + tid]);
        v = fmaxf(v, red[256 + tid]);
        v = fmaxf(v, red[384 + tid]);
        v = v * sFp[p0 + tid] + 2.0f;  // key in [0.95, 3.05] > 0: int-max valid
        atomicMax((int*)&g_spatch[(size_t)pair * P + p0 + tid],
                  __float_as_int(v));
    }
}

// ---------------------------------------------------------------------------
// Kernel 3: decode keys -> dist, then scores[n] = mean_m max_p,
// sp[n][p] = mean_m. dist = 0.5*sqrt(max(2 - 2*(key-2), 0)).
// ---------------------------------------------------------------------------
__global__ void reduce_k(float* __restrict__ scores) {
    const int n = blockIdx.x;
    const int p = threadIdx.x;
    float v[8];
    float s = 0.f;
    #pragma unroll
    for (int m = 0; m < 8; m++) {
        float key = g_spatch[(size_t)(n * 8 + m) * P + p];
        float c = key - 2.0f;
        v[m] = 0.5f * sqrtf(fmaxf(2.0f - 2.0f * c, 0.0f));
        s += v[m];
    }
    g_sp[n * P + p] = s * 0.125f;

    __shared__ int smax[8];
    if (p < 8) smax[p] = 0;  // dist >= 0 so int-compare == float-compare
    __syncthreads();
    #pragma unroll
    for (int m = 0; m < 8; m++) {
        float x = v[m];
        #pragma unroll
        for (int off = 16; off; off >>= 1)
            x = fmaxf(x, __shfl_xor_sync(0xffffffffu, x, off));
        if ((p & 31) == 0) atomicMax(&smax[m], __float_as_int(x));
    }
    __syncthreads();
    if (p == 0) {
        float t = 0.f;
        #pragma unroll
        for (int m = 0; m < 8; m++) t += __int_as_float(smax[m]);
        scores[n] = t * 0.125f;
    }
}

// ---------------------------------------------------------------------------
// Kernel 4: bilinear resize (8,32,32) -> (8,512,512).
// One block per output row; source rows staged in smem; each thread writes
// one float4 (4 pixels). grid = 8*512, block = 128.
// ---------------------------------------------------------------------------
__global__ void resize_k(float* __restrict__ out) {
    const int n = blockIdx.x >> 9;         // image
    const int r = blockIdx.x & (OH - 1);   // output row
    const int t = threadIdx.x;             // 0..127, pixels 4t..4t+3

    __shared__ float r0s[PW], r1s[PW];
    {
        float sy = (r + 0.5f) * ((float)PH / OH) - 0.5f;
        float y0f = floorf(sy);
        int y0 = min(max((int)y0f, 0), PH - 1);
        int y1 = min(max((int)y0f + 1, 0), PH - 1);
        const float* __restrict__ b = g_sp + n * (PH * PW);
        if (t < PW)            r0s[t] = b[y0 * PW + t];
        else if (t < 2 * PW)   r1s[t - PW] = b[y1 * PW + (t - PW)];
    }
    __syncthreads();

    float sy = (r + 0.5f) * ((float)PH / OH) - 0.5f;
    float wy = sy - floorf(sy);
    float4 o;
    float* op = &o.x;
    #pragma unroll
    for (int k = 0; k < 4; k++) {
        int c = 4 * t + k;
        float sx = (c + 0.5f) * ((float)PW / OW) - 0.5f;
        float x0f = floorf(sx);
        float wx = sx - x0f;
        int x0 = min(max((int)x0f, 0), PW - 1);
        int x1 = min(max((int)x0f + 1, 0), PW - 1);
        float top = r0s[x0] + (r0s[x1] - r0s[x0]) * wx;
        float bot = r1s[x0] + (r1s[x1] - r1s[x0]) * wx;
        op[k] = top + (bot - top) * wy;
    }
    *(float4*)(out + ((size_t)n * OH + r) * OW + 4 * t) = o;
}

// ---------------------------------------------------------------------------
extern "C" void kernel_launch(void* const* d_in, const int* in_sizes, int n_in,
                              void* d_out, int out_size) {
    (void)in_sizes; (void)n_in; (void)out_size;
    const float* feats  = (const float*)d_in[0];
    const float* nfeats = (const float*)d_in[1];
    float* out = (float*)d_out;  // [0..7] = scores, [8..] = scores_pixel

    cudaFuncSetAttribute(gemm_max_k,
                         cudaFuncAttributeMaxDynamicSharedMemorySize, SMEM_DYN);

    norm_k<<<(N1 + N2) * P, 192>>>(feats, nfeats);
    dim3 ggrid(P / BM, N1 * N2 * 2);  // 1024 units: (pblock, pair*2 + qhalf)
    gemm_max_k<<<ggrid, 256, SMEM_DYN>>>();
    reduce_k<<<N1, P>>>(out);
    resize_k<<<N1 * OH, 128>>>(out + N1);
}